// round 8
// baseline (speedup 1.0000x reference)
#include <cuda_runtime.h>
#include <math.h>

#define BB   8
#define SS   512
#define HH   1024
#define NHH  8
#define DHH  128
#define MM   (BB*SS)
#define IN3  3072
#define R2   1024
#define HD   512
#define G4   2048
#define INV_SCALE 0.051031036307982884f  /* 1/sqrt(128*3) */

__device__ float g_h1[MM*HH];
__device__ float g_qkv[MM*3*HH];
__device__ float g_posk[R2*HH];
__device__ float g_posq[R2*HH];
__device__ float g_scores[BB*NHH*SS*SS];
__device__ float g_ctx2[MM*HH];
__device__ float g_t1[MM*IN3];
__device__ float g_y[MM*HH];
__device__ float g_h2[MM*HH];
__device__ float g_h3[MM*HH];
__device__ float g_xw[2*MM*G4];

// C = A[M,K] * B[N,K]^T, optional bias/bias2/residual/scale/exact-GELU.
__global__ void sgemm_kernel(const float* __restrict__ A, const float* __restrict__ Bw,
                             float* __restrict__ C, int Md, int Nd, int Kd,
                             const float* __restrict__ bias, const float* __restrict__ bias2,
                             const float* __restrict__ res, float scale, int act,
                             long sA, long sB, int modB, long sC)
{
    __shared__ float As[16][132];
    __shared__ float Bs[16][132];
    int z = blockIdx.z;
    const float* Ab = A + (long)z * sA;
    const float* Bb = Bw + (long)(modB ? (z % modB) : z) * sB;
    float*       Cb = C + (long)z * sC;
    int tid = threadIdx.x;
    int m0 = blockIdx.y << 7, n0 = blockIdx.x << 7;
    int tx = tid & 15, ty = tid >> 4;
    float acc[8][8];
#pragma unroll
    for (int i = 0; i < 8; i++)
#pragma unroll
        for (int j = 0; j < 8; j++) acc[i][j] = 0.f;

    for (int k0 = 0; k0 < Kd; k0 += 16) {
#pragma unroll
        for (int i = 0; i < 8; i++) {
            int l = tid + (i << 8);
            int rr = l >> 4, kk = l & 15;
            As[kk][rr] = Ab[(long)(m0 + rr) * Kd + (k0 + kk)];
            Bs[kk][rr] = Bb[(long)(n0 + rr) * Kd + (k0 + kk)];
        }
        __syncthreads();
#pragma unroll
        for (int kk = 0; kk < 16; kk++) {
            float a[8], b[8];
#pragma unroll
            for (int i = 0; i < 8; i++) a[i] = As[kk][(ty << 3) + i];
#pragma unroll
            for (int j = 0; j < 8; j++) b[j] = Bs[kk][(tx << 3) + j];
#pragma unroll
            for (int i = 0; i < 8; i++)
#pragma unroll
                for (int j = 0; j < 8; j++) acc[i][j] = fmaf(a[i], b[j], acc[i][j]);
        }
        __syncthreads();
    }
#pragma unroll
    for (int i = 0; i < 8; i++) {
        int m = m0 + (ty << 3) + i;
#pragma unroll
        for (int j = 0; j < 8; j++) {
            int n = n0 + (tx << 3) + j;
            float v = acc[i][j];
            if (bias)  v += bias[n];
            if (bias2) v += bias2[n];
            if (res)   v += res[(long)z * sC + (long)m * Nd + n];
            v *= scale;
            if (act) v = 0.5f * v * (1.f + erff(v * 0.70710678118654752f));
            Cb[(long)m * Nd + n] = v;
        }
    }
}

// y[b,s,c] = x[b,s,c] + pos[s,c]
__global__ void add_pos_kernel(const float* __restrict__ x, const float* __restrict__ pos,
                               float* __restrict__ y)
{
    long i = (long)blockIdx.x * blockDim.x + threadIdx.x;
    int c = (int)(i & 1023);
    int ms = (int)(i >> 10);
    int s = ms & 511;
    y[i] = x[i] + pos[(long)s * HH + c];
}

__global__ void ln_kernel(const float* __restrict__ in, const float* __restrict__ gw,
                          const float* __restrict__ bw, float* __restrict__ out)
{
    int row = blockIdx.x;
    const float* xp = in + (long)row * HH;
    int tid = threadIdx.x;
    float v[4]; float s = 0.f, sq = 0.f;
#pragma unroll
    for (int i = 0; i < 4; i++) {
        int c = tid + (i << 8);
        float t = xp[c];
        v[i] = t; s += t; sq += t * t;
    }
#pragma unroll
    for (int o = 16; o > 0; o >>= 1) {
        s  += __shfl_xor_sync(0xffffffffu, s, o);
        sq += __shfl_xor_sync(0xffffffffu, sq, o);
    }
    __shared__ float red[18];
    int w = tid >> 5, l = tid & 31;
    if (l == 0) { red[w] = s; red[8 + w] = sq; }
    __syncthreads();
    if (tid == 0) {
        float ts = 0.f, tq = 0.f;
#pragma unroll
        for (int i = 0; i < 8; i++) { ts += red[i]; tq += red[8 + i]; }
        float mean = ts * (1.f / HH);
        float var  = tq * (1.f / HH) - mean * mean;
        red[16] = mean; red[17] = rsqrtf(var + 1e-7f);
    }
    __syncthreads();
    float mean = red[16], rstd = red[17];
    float* op = out + (long)row * HH;
#pragma unroll
    for (int i = 0; i < 4; i++) {
        int c = tid + (i << 8);
        op[c] = (v[i] - mean) * rstd * gw[c] + bw[c];
    }
}

// Fused scores + c2p + p2c + softmax.  ALL buffers passed as real device pointers.
// score[q,k] = q.k + q.pos_key[q-k+512] + k.pos_q[q-k+512]  (q, pos_q pre-scaled)
__global__ void attn_kernel(const float* __restrict__ qkv, const float* __restrict__ posk,
                            const float* __restrict__ posq, float* __restrict__ scores,
                            const float* __restrict__ qb)
{
    int row = blockIdx.x;
    int z = row >> 9, q = row & 511;
    int b = z >> 3, h = z & 7;
    int tid = threadIdx.x;
    __shared__ float qs[DHH];
    __shared__ float red[17];
    const float* qkvq = qkv + ((long)(b * SS + q)) * (3 * HH) + h * DHH;
    if (tid < DHH) qs[tid] = (qkvq[tid] + qb[h * DHH + tid]) * INV_SCALE;
    __syncthreads();

    const float4* qs4 = (const float4*)qs;
    float val[2]; float mx = -1e30f;
#pragma unroll
    for (int i = 0; i < 2; i++) {
        int k = tid + (i << 8);
        int rel = q - k + 512;
        const float4* kr4 = (const float4*)(qkv + ((long)(b * SS + k)) * (3 * HH) + HH + h * DHH);
        const float4* ck4 = (const float4*)(posk + (long)rel * HH + h * DHH);
        const float4* pq4 = (const float4*)(posq + (long)rel * HH + h * DHH);
        float s = 0.f;
#pragma unroll 8
        for (int d = 0; d < 32; d++) {
            float4 kv = kr4[d], cv = ck4[d], pv = pq4[d], qv = qs4[d];
            s += qv.x * (kv.x + cv.x) + kv.x * pv.x;
            s += qv.y * (kv.y + cv.y) + kv.y * pv.y;
            s += qv.z * (kv.z + cv.z) + kv.z * pv.z;
            s += qv.w * (kv.w + cv.w) + kv.w * pv.w;
        }
        val[i] = s; mx = fmaxf(mx, s);
    }
    int w = tid >> 5, l = tid & 31;
#pragma unroll
    for (int o = 16; o > 0; o >>= 1) mx = fmaxf(mx, __shfl_xor_sync(0xffffffffu, mx, o));
    if (l == 0) red[w] = mx;
    __syncthreads();
    if (tid == 0) {
        float m2 = red[0];
#pragma unroll
        for (int i = 1; i < 8; i++) m2 = fmaxf(m2, red[i]);
        red[16] = m2;
    }
    __syncthreads();
    mx = red[16];
    float e0 = __expf(val[0] - mx), e1 = __expf(val[1] - mx);
    float s = e0 + e1;
#pragma unroll
    for (int o = 16; o > 0; o >>= 1) s += __shfl_xor_sync(0xffffffffu, s, o);
    __syncthreads();
    if (l == 0) red[w] = s;
    __syncthreads();
    if (tid == 0) {
        float t = 0.f;
#pragma unroll
        for (int i = 0; i < 8; i++) t += red[i];
        red[16] = 1.f / t;
    }
    __syncthreads();
    float inv = red[16];
    float* srow = scores + (long)row * SS;
    srow[tid] = e0 * inv;
    srow[tid + 256] = e1 * inv;
}

// ctx2[b,q,h*128+d] = sum_k probs[z,q,k] * qkv_v[b,k,h*128+d]  + vb
__global__ void ctx_naive_kernel(const float* __restrict__ qkv, const float* __restrict__ scores,
                                 float* __restrict__ ctx2, const float* __restrict__ vb)
{
    __shared__ float ps[SS];
    int row = blockIdx.x;
    int z = row >> 9, q = row & 511;
    int b = z >> 3, h = z & 7;
    int tid = threadIdx.x;
    const float* srow = scores + (long)row * SS;
    for (int k = tid; k < SS; k += 128) ps[k] = srow[k];
    __syncthreads();
    int c = h * DHH + tid;
    const float* vp = qkv + (long)b * SS * (3 * HH) + 2 * HH + c;
    float acc = 0.f;
#pragma unroll 4
    for (int k = 0; k < SS; k++)
        acc = fmaf(ps[k], vp[(long)k * (3 * HH)], acc);
    acc += vb[c];
    ctx2[((long)(b * SS + q)) * HH + c] = acc;
}

// LSTM: one block per (dir, batch), zero inter-block communication.
__global__ void LSTMDisentangledAttention_15049565405471_kernel(
    const float* __restrict__ xw,
    const float* __restrict__ WhhF,
    const float* __restrict__ WhhR,
    float* __restrict__ out)
{
    __shared__ float hs[HD];
    int dir = blockIdx.x >> 3;
    int b   = blockIdx.x & 7;
    int u   = threadIdx.x;
    const float* Whh = dir ? WhhR : WhhF;
    const float* xwd = xw + (long)dir * MM * G4;
    const float* wi = Whh + (long)u * HD;
    const float* wf = Whh + (long)(512  + u) * HD;
    const float* wg = Whh + (long)(1024 + u) * HD;
    const float* wo = Whh + (long)(1536 + u) * HD;

    float c = 0.f;
    hs[u] = 0.f;
    __syncthreads();

    for (int t = 0; t < SS; t++) {
        int sI = dir ? (SS - 1 - t) : t;
        const float* xr = xwd + (long)(b * SS + sI) * G4;
        float ai = xr[u], af = xr[512 + u], ag = xr[1024 + u], ao = xr[1536 + u];
#pragma unroll 4
        for (int j = 0; j < HD; j++) {
            float hv = hs[j];
            ai = fmaf(wi[j], hv, ai);
            af = fmaf(wf[j], hv, af);
            ag = fmaf(wg[j], hv, ag);
            ao = fmaf(wo[j], hv, ao);
        }
        float ig = 1.f / (1.f + expf(-ai));
        float fg = 1.f / (1.f + expf(-af));
        float gg = tanhf(ag);
        float og = 1.f / (1.f + expf(-ao));
        c = fg * c + ig * gg;
        float hv = og * tanhf(c);
        __syncthreads();
        hs[u] = hv;
        out[(long)(b * SS + sI) * HH + dir * HD + u] = hv;
        __syncthreads();
    }
}

extern "C" void kernel_launch(void* const* d_in, const int* in_sizes, int n_in,
                              void* d_out, int out_size)
{
    (void)in_sizes; (void)n_in; (void)out_size;
    const float* x       = (const float*)d_in[0];
    const float* pos_emb = (const float*)d_in[1];
    const float* emb_g   = (const float*)d_in[2];
    const float* emb_b   = (const float*)d_in[3];
    const float* in_w    = (const float*)d_in[4];
    const float* q_bias  = (const float*)d_in[5];
    const float* v_bias  = (const float*)d_in[6];
    const float* rel_emb = (const float*)d_in[7];
    const float* posk_w  = (const float*)d_in[8];
    const float* posq_w  = (const float*)d_in[9];
    const float* posq_b  = (const float*)d_in[10];
    const float* ao_w    = (const float*)d_in[11];
    const float* ao_b    = (const float*)d_in[12];
    const float* aln_g   = (const float*)d_in[13];
    const float* aln_b   = (const float*)d_in[14];
    const float* it_w    = (const float*)d_in[15];
    const float* it_b    = (const float*)d_in[16];
    const float* fo_w    = (const float*)d_in[17];
    const float* fo_b    = (const float*)d_in[18];
    const float* fln_g   = (const float*)d_in[19];
    const float* fln_b   = (const float*)d_in[20];
    const float* Wih_f   = (const float*)d_in[21];
    const float* Whh_f   = (const float*)d_in[22];
    const float* bih_f   = (const float*)d_in[23];
    const float* bhh_f   = (const float*)d_in[24];
    const float* Wih_r   = (const float*)d_in[25];
    const float* Whh_r   = (const float*)d_in[26];
    const float* bih_r   = (const float*)d_in[27];
    const float* bhh_r   = (const float*)d_in[28];
    float* out = (float*)d_out;

    // THE FIX: resolve true device addresses of all scratch buffers.
    // Passing a __device__ symbol from host code yields the HOST shadow address
    // (silently dereferenceable on GB300 via ATS) — scratch was split between
    // host shadow memory (pointer paths) and device memory (symbol paths).
    float *h1, *qkv, *posk, *posq, *scores, *ctx2, *t1, *y, *h2, *h3, *xw;
    cudaGetSymbolAddress((void**)&h1,     g_h1);
    cudaGetSymbolAddress((void**)&qkv,    g_qkv);
    cudaGetSymbolAddress((void**)&posk,   g_posk);
    cudaGetSymbolAddress((void**)&posq,   g_posq);
    cudaGetSymbolAddress((void**)&scores, g_scores);
    cudaGetSymbolAddress((void**)&ctx2,   g_ctx2);
    cudaGetSymbolAddress((void**)&t1,     g_t1);
    cudaGetSymbolAddress((void**)&y,      g_y);
    cudaGetSymbolAddress((void**)&h2,     g_h2);
    cudaGetSymbolAddress((void**)&h3,     g_h3);
    cudaGetSymbolAddress((void**)&xw,     g_xw);

    // 1. h1 = LN(x + pos_emb)
    add_pos_kernel<<<MM*HH/256, 256>>>(x, pos_emb, y);
    ln_kernel<<<MM, 256>>>(y, emb_g, emb_b, h1);
    // 2. qkv = h1 @ in_w^T
    sgemm_kernel<<<dim3(IN3/128, MM/128, 1), 256>>>(h1, in_w, qkv, MM, IN3, HH,
        0, 0, 0, 1.f, 0, 0, 0, 0, 0);
    // 3. pos tables (pos_q pre-scaled by 1/sqrt(384))
    sgemm_kernel<<<dim3(HH/128, R2/128, 1), 256>>>(rel_emb, posk_w, posk, R2, HH, HH,
        0, 0, 0, 1.f, 0, 0, 0, 0, 0);
    sgemm_kernel<<<dim3(HH/128, R2/128, 1), 256>>>(rel_emb, posq_w, posq, R2, HH, HH,
        posq_b, 0, 0, INV_SCALE, 0, 0, 0, 0, 0);
    // 4. fused scores + c2p + p2c + softmax
    attn_kernel<<<BB*NHH*SS, 256>>>(qkv, posk, posq, scores, q_bias);
    // 5. ctx directly from qkv (merged layout)
    ctx_naive_kernel<<<BB*NHH*SS, 128>>>(qkv, scores, ctx2, v_bias);
    // 6. attn out + residual + LN
    sgemm_kernel<<<dim3(HH/128, MM/128, 1), 256>>>(ctx2, ao_w, y, MM, HH, HH,
        ao_b, 0, h1, 1.f, 0, 0, 0, 0, (long)MM*HH);
    ln_kernel<<<MM, 256>>>(y, aln_g, aln_b, h2);
    // 7. FFN
    sgemm_kernel<<<dim3(IN3/128, MM/128, 1), 256>>>(h2, it_w, t1, MM, IN3, HH,
        it_b, 0, 0, 1.f, 1, 0, 0, 0, 0);
    sgemm_kernel<<<dim3(HH/128, MM/128, 1), 256>>>(t1, fo_w, y, MM, HH, IN3,
        fo_b, 0, h2, 1.f, 0, 0, 0, 0, (long)MM*HH);
    ln_kernel<<<MM, 256>>>(y, fln_g, fln_b, h3);
    // 8. LSTM input projections
    sgemm_kernel<<<dim3(G4/128, MM/128, 1), 256>>>(h3, Wih_f, xw, MM, G4, HH,
        bih_f, bhh_f, 0, 1.f, 0, 0, 0, 0, 0);
    sgemm_kernel<<<dim3(G4/128, MM/128, 1), 256>>>(h3, Wih_r, xw + (long)MM*G4, MM, G4, HH,
        bih_r, bhh_r, 0, 1.f, 0, 0, 0, 0, 0);
    // 9. bidirectional LSTM
    LSTMDisentangledAttention_15049565405471_kernel<<<16, 512>>>(xw, Whh_f, Whh_r, out);
}

// round 9
// speedup vs baseline: 7.5810x; 7.5810x over previous
#include <cuda_runtime.h>
#include <math.h>

#define BB   8
#define SS   512
#define HH   1024
#define NHH  8
#define DHH  128
#define MM   (BB*SS)
#define IN3  3072
#define R2   1024
#define HD   512
#define G4   2048
#define INV_SCALE 0.051031036307982884f  /* 1/sqrt(128*3) */

__device__ float g_h1[MM*HH];
__device__ float g_qkv[MM*3*HH];
__device__ float g_posk[R2*HH];
__device__ float g_posq[R2*HH];
__device__ float g_scores[BB*NHH*SS*SS];
__device__ float g_ctx2[MM*HH];
__device__ float g_t1[MM*IN3];
__device__ float g_y[MM*HH];
__device__ float g_h2[MM*HH];
__device__ float g_h3[MM*HH];
__device__ float g_xw[2*MM*G4];
__device__ float g_whhT[2*HD*G4];   /* [dir][j][gate*512+u] transposed Whh */

// C = A[M,K] * B[N,K]^T, optional bias/bias2/residual/scale/exact-GELU.
__global__ void sgemm_kernel(const float* __restrict__ A, const float* __restrict__ Bw,
                             float* __restrict__ C, int Md, int Nd, int Kd,
                             const float* __restrict__ bias, const float* __restrict__ bias2,
                             const float* __restrict__ res, float scale, int act,
                             long sA, long sB, int modB, long sC)
{
    __shared__ float As[16][132];
    __shared__ float Bs[16][132];
    int z = blockIdx.z;
    const float* Ab = A + (long)z * sA;
    const float* Bb = Bw + (long)(modB ? (z % modB) : z) * sB;
    float*       Cb = C + (long)z * sC;
    int tid = threadIdx.x;
    int m0 = blockIdx.y << 7, n0 = blockIdx.x << 7;
    int tx = tid & 15, ty = tid >> 4;
    float acc[8][8];
#pragma unroll
    for (int i = 0; i < 8; i++)
#pragma unroll
        for (int j = 0; j < 8; j++) acc[i][j] = 0.f;

    for (int k0 = 0; k0 < Kd; k0 += 16) {
#pragma unroll
        for (int i = 0; i < 8; i++) {
            int l = tid + (i << 8);
            int rr = l >> 4, kk = l & 15;
            As[kk][rr] = Ab[(long)(m0 + rr) * Kd + (k0 + kk)];
            Bs[kk][rr] = Bb[(long)(n0 + rr) * Kd + (k0 + kk)];
        }
        __syncthreads();
#pragma unroll
        for (int kk = 0; kk < 16; kk++) {
            float a[8], b[8];
#pragma unroll
            for (int i = 0; i < 8; i++) a[i] = As[kk][(ty << 3) + i];
#pragma unroll
            for (int j = 0; j < 8; j++) b[j] = Bs[kk][(tx << 3) + j];
#pragma unroll
            for (int i = 0; i < 8; i++)
#pragma unroll
                for (int j = 0; j < 8; j++) acc[i][j] = fmaf(a[i], b[j], acc[i][j]);
        }
        __syncthreads();
    }
#pragma unroll
    for (int i = 0; i < 8; i++) {
        int m = m0 + (ty << 3) + i;
#pragma unroll
        for (int j = 0; j < 8; j++) {
            int n = n0 + (tx << 3) + j;
            float v = acc[i][j];
            if (bias)  v += bias[n];
            if (bias2) v += bias2[n];
            if (res)   v += res[(long)z * sC + (long)m * Nd + n];
            v *= scale;
            if (act) v = 0.5f * v * (1.f + erff(v * 0.70710678118654752f));
            Cb[(long)m * Nd + n] = v;
        }
    }
}

// y[b,s,c] = x[b,s,c] + pos[s,c]
__global__ void add_pos_kernel(const float* __restrict__ x, const float* __restrict__ pos,
                               float* __restrict__ y)
{
    long i = (long)blockIdx.x * blockDim.x + threadIdx.x;
    int c = (int)(i & 1023);
    int ms = (int)(i >> 10);
    int s = ms & 511;
    y[i] = x[i] + pos[(long)s * HH + c];
}

__global__ void ln_kernel(const float* __restrict__ in, const float* __restrict__ gw,
                          const float* __restrict__ bw, float* __restrict__ out)
{
    int row = blockIdx.x;
    const float* xp = in + (long)row * HH;
    int tid = threadIdx.x;
    float v[4]; float s = 0.f, sq = 0.f;
#pragma unroll
    for (int i = 0; i < 4; i++) {
        int c = tid + (i << 8);
        float t = xp[c];
        v[i] = t; s += t; sq += t * t;
    }
#pragma unroll
    for (int o = 16; o > 0; o >>= 1) {
        s  += __shfl_xor_sync(0xffffffffu, s, o);
        sq += __shfl_xor_sync(0xffffffffu, sq, o);
    }
    __shared__ float red[18];
    int w = tid >> 5, l = tid & 31;
    if (l == 0) { red[w] = s; red[8 + w] = sq; }
    __syncthreads();
    if (tid == 0) {
        float ts = 0.f, tq = 0.f;
#pragma unroll
        for (int i = 0; i < 8; i++) { ts += red[i]; tq += red[8 + i]; }
        float mean = ts * (1.f / HH);
        float var  = tq * (1.f / HH) - mean * mean;
        red[16] = mean; red[17] = rsqrtf(var + 1e-7f);
    }
    __syncthreads();
    float mean = red[16], rstd = red[17];
    float* op = out + (long)row * HH;
#pragma unroll
    for (int i = 0; i < 4; i++) {
        int c = tid + (i << 8);
        op[c] = (v[i] - mean) * rstd * gw[c] + bw[c];
    }
}

// Fused scores + c2p + p2c + softmax, COALESCED: one warp per k, lanes over d.
// score[q,k] = q.k + q.pos_key[q-k+512] + k.pos_q[q-k+512]  (q, pos_q pre-scaled)
__global__ void attn_kernel(const float* __restrict__ qkv, const float* __restrict__ posk,
                            const float* __restrict__ posq, float* __restrict__ scores,
                            const float* __restrict__ qb)
{
    int row = blockIdx.x;
    int z = row >> 9, q = row & 511;
    int b = z >> 3, h = z & 7;
    int tid = threadIdx.x;
    int w = tid >> 5, lane = tid & 31;
    __shared__ float qs[DHH];
    __shared__ float sc[SS];
    __shared__ float red[17];
    const float* qkvq = qkv + ((long)(b * SS + q)) * (3 * HH) + h * DHH;
    if (tid < DHH) qs[tid] = (qkvq[tid] + qb[h * DHH + tid]) * INV_SCALE;
    __syncthreads();
    float4 qv = ((const float4*)qs)[lane];

#pragma unroll 2
    for (int i = 0; i < 64; i++) {
        int k = (w << 6) + i;
        int rel = q - k + 512;
        float4 kv = ((const float4*)(qkv + ((long)(b * SS + k)) * (3 * HH) + HH + h * DHH))[lane];
        float4 cv = ((const float4*)(posk + (long)rel * HH + h * DHH))[lane];
        float4 pv = ((const float4*)(posq + (long)rel * HH + h * DHH))[lane];
        float s = qv.x * (kv.x + cv.x) + kv.x * pv.x
                + qv.y * (kv.y + cv.y) + kv.y * pv.y
                + qv.z * (kv.z + cv.z) + kv.z * pv.z
                + qv.w * (kv.w + cv.w) + kv.w * pv.w;
#pragma unroll
        for (int o = 16; o > 0; o >>= 1) s += __shfl_xor_sync(0xffffffffu, s, o);
        if (lane == 0) sc[k] = s;
    }
    __syncthreads();

    // softmax over sc[512] with 256 threads
    float v0 = sc[tid], v1 = sc[tid + 256];
    float mx = fmaxf(v0, v1);
#pragma unroll
    for (int o = 16; o > 0; o >>= 1) mx = fmaxf(mx, __shfl_xor_sync(0xffffffffu, mx, o));
    if (lane == 0) red[w] = mx;
    __syncthreads();
    if (tid == 0) {
        float m2 = red[0];
#pragma unroll
        for (int i = 1; i < 8; i++) m2 = fmaxf(m2, red[i]);
        red[16] = m2;
    }
    __syncthreads();
    mx = red[16];
    float e0 = __expf(v0 - mx), e1 = __expf(v1 - mx);
    float s = e0 + e1;
#pragma unroll
    for (int o = 16; o > 0; o >>= 1) s += __shfl_xor_sync(0xffffffffu, s, o);
    __syncthreads();
    if (lane == 0) red[w] = s;
    __syncthreads();
    if (tid == 0) {
        float t = 0.f;
#pragma unroll
        for (int i = 0; i < 8; i++) t += red[i];
        red[16] = 1.f / t;
    }
    __syncthreads();
    float inv = red[16];
    float* srow = scores + (long)row * SS;
    srow[tid] = e0 * inv;
    srow[tid + 256] = e1 * inv;
}

// ctx2[b,q,h*128+d] = sum_k probs[z,q,k] * qkv_v[b,k,h*128+d]  + vb
__global__ void ctx_naive_kernel(const float* __restrict__ qkv, const float* __restrict__ scores,
                                 float* __restrict__ ctx2, const float* __restrict__ vb)
{
    __shared__ float ps[SS];
    int row = blockIdx.x;
    int z = row >> 9, q = row & 511;
    int b = z >> 3, h = z & 7;
    int tid = threadIdx.x;
    const float* srow = scores + (long)row * SS;
    for (int k = tid; k < SS; k += 128) ps[k] = srow[k];
    __syncthreads();
    int c = h * DHH + tid;
    const float* vp = qkv + (long)b * SS * (3 * HH) + 2 * HH + c;
    float acc = 0.f;
#pragma unroll 4
    for (int k = 0; k < SS; k++)
        acc = fmaf(ps[k], vp[(long)k * (3 * HH)], acc);
    acc += vb[c];
    ctx2[((long)(b * SS + q)) * HH + c] = acc;
}

// whhT[dir][j*G4 + r] = Whh_dir[r*HD + j]   (coalesced-write one-time transpose)
__global__ void transpose_whh_kernel(const float* __restrict__ Wf, const float* __restrict__ Wr,
                                     float* __restrict__ wT)
{
    long i = (long)blockIdx.x * blockDim.x + threadIdx.x;   // 2 * 512 * 2048
    int dir = (int)(i >> 20);
    long rem = i & ((1L << 20) - 1);
    int j = (int)(rem >> 11);          // 0..511
    int r = (int)(rem & 2047);         // 0..2047
    const float* W = dir ? Wr : Wf;
    wT[i] = W[(long)r * HD + j];
}

// LSTM: one block per (dir, batch). Coalesced WhhT loads (lane-consecutive u).
__global__ void LSTMDisentangledAttention_15049565405471_kernel(
    const float* __restrict__ xw,
    const float* __restrict__ whhT,
    float* __restrict__ out)
{
    __shared__ float hs[HD];
    int dir = blockIdx.x >> 3;
    int b   = blockIdx.x & 7;
    int u   = threadIdx.x;
    const float* wT  = whhT + (long)dir * HD * G4;
    const float* xwd = xw + (long)dir * MM * G4;

    float c = 0.f;
    hs[u] = 0.f;
    __syncthreads();

    for (int t = 0; t < SS; t++) {
        int sI = dir ? (SS - 1 - t) : t;
        const float* xr = xwd + (long)(b * SS + sI) * G4;
        float ai = xr[u], af = xr[512 + u], ag = xr[1024 + u], ao = xr[1536 + u];
#pragma unroll 4
        for (int j = 0; j < HD; j++) {
            float hv = hs[j];
            const float* wrow = wT + (long)j * G4;
            ai = fmaf(wrow[u],        hv, ai);
            af = fmaf(wrow[512 + u],  hv, af);
            ag = fmaf(wrow[1024 + u], hv, ag);
            ao = fmaf(wrow[1536 + u], hv, ao);
        }
        float ig = 1.f / (1.f + expf(-ai));
        float fg = 1.f / (1.f + expf(-af));
        float gg = tanhf(ag);
        float og = 1.f / (1.f + expf(-ao));
        c = fg * c + ig * gg;
        float hv = og * tanhf(c);
        __syncthreads();
        hs[u] = hv;
        out[(long)(b * SS + sI) * HH + dir * HD + u] = hv;
        __syncthreads();
    }
}

extern "C" void kernel_launch(void* const* d_in, const int* in_sizes, int n_in,
                              void* d_out, int out_size)
{
    (void)in_sizes; (void)n_in; (void)out_size;
    const float* x       = (const float*)d_in[0];
    const float* pos_emb = (const float*)d_in[1];
    const float* emb_g   = (const float*)d_in[2];
    const float* emb_b   = (const float*)d_in[3];
    const float* in_w    = (const float*)d_in[4];
    const float* q_bias  = (const float*)d_in[5];
    const float* v_bias  = (const float*)d_in[6];
    const float* rel_emb = (const float*)d_in[7];
    const float* posk_w  = (const float*)d_in[8];
    const float* posq_w  = (const float*)d_in[9];
    const float* posq_b  = (const float*)d_in[10];
    const float* ao_w    = (const float*)d_in[11];
    const float* ao_b    = (const float*)d_in[12];
    const float* aln_g   = (const float*)d_in[13];
    const float* aln_b   = (const float*)d_in[14];
    const float* it_w    = (const float*)d_in[15];
    const float* it_b    = (const float*)d_in[16];
    const float* fo_w    = (const float*)d_in[17];
    const float* fo_b    = (const float*)d_in[18];
    const float* fln_g   = (const float*)d_in[19];
    const float* fln_b   = (const float*)d_in[20];
    const float* Wih_f   = (const float*)d_in[21];
    const float* Whh_f   = (const float*)d_in[22];
    const float* bih_f   = (const float*)d_in[23];
    const float* bhh_f   = (const float*)d_in[24];
    const float* Wih_r   = (const float*)d_in[25];
    const float* Whh_r   = (const float*)d_in[26];
    const float* bih_r   = (const float*)d_in[27];
    const float* bhh_r   = (const float*)d_in[28];
    float* out = (float*)d_out;

    float *h1, *qkv, *posk, *posq, *scores, *ctx2, *t1, *y, *h2, *h3, *xw, *whhT;
    cudaGetSymbolAddress((void**)&h1,     g_h1);
    cudaGetSymbolAddress((void**)&qkv,    g_qkv);
    cudaGetSymbolAddress((void**)&posk,   g_posk);
    cudaGetSymbolAddress((void**)&posq,   g_posq);
    cudaGetSymbolAddress((void**)&scores, g_scores);
    cudaGetSymbolAddress((void**)&ctx2,   g_ctx2);
    cudaGetSymbolAddress((void**)&t1,     g_t1);
    cudaGetSymbolAddress((void**)&y,      g_y);
    cudaGetSymbolAddress((void**)&h2,     g_h2);
    cudaGetSymbolAddress((void**)&h3,     g_h3);
    cudaGetSymbolAddress((void**)&xw,     g_xw);
    cudaGetSymbolAddress((void**)&whhT,   g_whhT);

    // 1. h1 = LN(x + pos_emb)
    add_pos_kernel<<<MM*HH/256, 256>>>(x, pos_emb, y);
    ln_kernel<<<MM, 256>>>(y, emb_g, emb_b, h1);
    // 2. qkv = h1 @ in_w^T
    sgemm_kernel<<<dim3(IN3/128, MM/128, 1), 256>>>(h1, in_w, qkv, MM, IN3, HH,
        0, 0, 0, 1.f, 0, 0, 0, 0, 0);
    // 3. pos tables (pos_q pre-scaled by 1/sqrt(384))
    sgemm_kernel<<<dim3(HH/128, R2/128, 1), 256>>>(rel_emb, posk_w, posk, R2, HH, HH,
        0, 0, 0, 1.f, 0, 0, 0, 0, 0);
    sgemm_kernel<<<dim3(HH/128, R2/128, 1), 256>>>(rel_emb, posq_w, posq, R2, HH, HH,
        posq_b, 0, 0, INV_SCALE, 0, 0, 0, 0, 0);
    // also prep LSTM weight transpose (independent; overlaps nothing but cheap)
    transpose_whh_kernel<<<2*HD*G4/256, 256>>>(Whh_f, Whh_r, whhT);
    // 4. fused scores + c2p + p2c + softmax (coalesced warp-per-k)
    attn_kernel<<<BB*NHH*SS, 256>>>(qkv, posk, posq, scores, q_bias);
    // 5. ctx directly from qkv (merged layout)
    ctx_naive_kernel<<<BB*NHH*SS, 128>>>(qkv, scores, ctx2, v_bias);
    // 6. attn out + residual + LN
    sgemm_kernel<<<dim3(HH/128, MM/128, 1), 256>>>(ctx2, ao_w, y, MM, HH, HH,
        ao_b, 0, h1, 1.f, 0, 0, 0, 0, (long)MM*HH);
    ln_kernel<<<MM, 256>>>(y, aln_g, aln_b, h2);
    // 7. FFN
    sgemm_kernel<<<dim3(IN3/128, MM/128, 1), 256>>>(h2, it_w, t1, MM, IN3, HH,
        it_b, 0, 0, 1.f, 1, 0, 0, 0, 0);
    sgemm_kernel<<<dim3(HH/128, MM/128, 1), 256>>>(t1, fo_w, y, MM, HH, IN3,
        fo_b, 0, h2, 1.f, 0, 0, 0, 0, (long)MM*HH);
    ln_kernel<<<MM, 256>>>(y, fln_g, fln_b, h3);
    // 8. LSTM input projections
    sgemm_kernel<<<dim3(G4/128, MM/128, 1), 256>>>(h3, Wih_f, xw, MM, G4, HH,
        bih_f, bhh_f, 0, 1.f, 0, 0, 0, 0, 0);
    sgemm_kernel<<<dim3(G4/128, MM/128, 1), 256>>>(h3, Wih_r, xw + (long)MM*G4, MM, G4, HH,
        bih_r, bhh_r, 0, 1.f, 0, 0, 0, 0, 0);
    // 9. bidirectional LSTM (coalesced weights)
    LSTMDisentangledAttention_15049565405471_kernel<<<16, 512>>>(xw, whhT, out);
}

// round 10
// speedup vs baseline: 33.1543x; 4.3733x over previous
#include <cuda_runtime.h>
#include <math.h>

#define BB   8
#define SS   512
#define HH   1024
#define NHH  8
#define DHH  128
#define MM   (BB*SS)
#define IN3  3072
#define R2   1024
#define HD   512
#define G4   2048
#define INV_SCALE 0.051031036307982884f  /* 1/sqrt(128*3) */

__device__ float g_h1[MM*HH];
__device__ float g_qkv[MM*3*HH];
__device__ float g_posk[R2*HH];
__device__ float g_posq[R2*HH];
__device__ float g_scores[BB*NHH*SS*SS];
__device__ float g_ctx2[MM*HH];
__device__ float g_t1[MM*IN3];
__device__ float g_y[MM*HH];
__device__ float g_h2[MM*HH];
__device__ float g_h3[MM*HH];
__device__ float g_xw[2*MM*G4];
__device__ float g_hseq[2*513*BB*HD];   /* write-once h sequence per direction */
__device__ unsigned int g_bar;

// C = A[M,K] * B[N,K]^T, optional bias/bias2/residual/scale/exact-GELU.
__global__ void sgemm_kernel(const float* __restrict__ A, const float* __restrict__ Bw,
                             float* __restrict__ C, int Md, int Nd, int Kd,
                             const float* __restrict__ bias, const float* __restrict__ bias2,
                             const float* __restrict__ res, float scale, int act,
                             long sA, long sB, int modB, long sC)
{
    __shared__ float As[16][132];
    __shared__ float Bs[16][132];
    int z = blockIdx.z;
    const float* Ab = A + (long)z * sA;
    const float* Bb = Bw + (long)(modB ? (z % modB) : z) * sB;
    float*       Cb = C + (long)z * sC;
    int tid = threadIdx.x;
    int m0 = blockIdx.y << 7, n0 = blockIdx.x << 7;
    int tx = tid & 15, ty = tid >> 4;
    float acc[8][8];
#pragma unroll
    for (int i = 0; i < 8; i++)
#pragma unroll
        for (int j = 0; j < 8; j++) acc[i][j] = 0.f;

    for (int k0 = 0; k0 < Kd; k0 += 16) {
#pragma unroll
        for (int i = 0; i < 8; i++) {
            int l = tid + (i << 8);
            int rr = l >> 4, kk = l & 15;
            As[kk][rr] = Ab[(long)(m0 + rr) * Kd + (k0 + kk)];
            Bs[kk][rr] = Bb[(long)(n0 + rr) * Kd + (k0 + kk)];
        }
        __syncthreads();
#pragma unroll
        for (int kk = 0; kk < 16; kk++) {
            float a[8], b[8];
#pragma unroll
            for (int i = 0; i < 8; i++) a[i] = As[kk][(ty << 3) + i];
#pragma unroll
            for (int j = 0; j < 8; j++) b[j] = Bs[kk][(tx << 3) + j];
#pragma unroll
            for (int i = 0; i < 8; i++)
#pragma unroll
                for (int j = 0; j < 8; j++) acc[i][j] = fmaf(a[i], b[j], acc[i][j]);
        }
        __syncthreads();
    }
#pragma unroll
    for (int i = 0; i < 8; i++) {
        int m = m0 + (ty << 3) + i;
#pragma unroll
        for (int j = 0; j < 8; j++) {
            int n = n0 + (tx << 3) + j;
            float v = acc[i][j];
            if (bias)  v += bias[n];
            if (bias2) v += bias2[n];
            if (res)   v += res[(long)z * sC + (long)m * Nd + n];
            v *= scale;
            if (act) v = 0.5f * v * (1.f + erff(v * 0.70710678118654752f));
            Cb[(long)m * Nd + n] = v;
        }
    }
}

// y[b,s,c] = x[b,s,c] + pos[s,c]
__global__ void add_pos_kernel(const float* __restrict__ x, const float* __restrict__ pos,
                               float* __restrict__ y)
{
    long i = (long)blockIdx.x * blockDim.x + threadIdx.x;
    int c = (int)(i & 1023);
    int ms = (int)(i >> 10);
    int s = ms & 511;
    y[i] = x[i] + pos[(long)s * HH + c];
}

__global__ void ln_kernel(const float* __restrict__ in, const float* __restrict__ gw,
                          const float* __restrict__ bw, float* __restrict__ out)
{
    int row = blockIdx.x;
    const float* xp = in + (long)row * HH;
    int tid = threadIdx.x;
    float v[4]; float s = 0.f, sq = 0.f;
#pragma unroll
    for (int i = 0; i < 4; i++) {
        int c = tid + (i << 8);
        float t = xp[c];
        v[i] = t; s += t; sq += t * t;
    }
#pragma unroll
    for (int o = 16; o > 0; o >>= 1) {
        s  += __shfl_xor_sync(0xffffffffu, s, o);
        sq += __shfl_xor_sync(0xffffffffu, sq, o);
    }
    __shared__ float red[18];
    int w = tid >> 5, l = tid & 31;
    if (l == 0) { red[w] = s; red[8 + w] = sq; }
    __syncthreads();
    if (tid == 0) {
        float ts = 0.f, tq = 0.f;
#pragma unroll
        for (int i = 0; i < 8; i++) { ts += red[i]; tq += red[8 + i]; }
        float mean = ts * (1.f / HH);
        float var  = tq * (1.f / HH) - mean * mean;
        red[16] = mean; red[17] = rsqrtf(var + 1e-7f);
    }
    __syncthreads();
    float mean = red[16], rstd = red[17];
    float* op = out + (long)row * HH;
#pragma unroll
    for (int i = 0; i < 4; i++) {
        int c = tid + (i << 8);
        op[c] = (v[i] - mean) * rstd * gw[c] + bw[c];
    }
}

// Fused scores + c2p + p2c + softmax, coalesced warp-per-k.
__global__ void attn_kernel(const float* __restrict__ qkv, const float* __restrict__ posk,
                            const float* __restrict__ posq, float* __restrict__ scores,
                            const float* __restrict__ qb)
{
    int row = blockIdx.x;
    int z = row >> 9, q = row & 511;
    int b = z >> 3, h = z & 7;
    int tid = threadIdx.x;
    int w = tid >> 5, lane = tid & 31;
    __shared__ float qs[DHH];
    __shared__ float sc[SS];
    __shared__ float red[17];
    const float* qkvq = qkv + ((long)(b * SS + q)) * (3 * HH) + h * DHH;
    if (tid < DHH) qs[tid] = (qkvq[tid] + qb[h * DHH + tid]) * INV_SCALE;
    __syncthreads();
    float4 qv = ((const float4*)qs)[lane];

#pragma unroll 2
    for (int i = 0; i < 64; i++) {
        int k = (w << 6) + i;
        int rel = q - k + 512;
        float4 kv = ((const float4*)(qkv + ((long)(b * SS + k)) * (3 * HH) + HH + h * DHH))[lane];
        float4 cv = ((const float4*)(posk + (long)rel * HH + h * DHH))[lane];
        float4 pv = ((const float4*)(posq + (long)rel * HH + h * DHH))[lane];
        float s = qv.x * (kv.x + cv.x) + kv.x * pv.x
                + qv.y * (kv.y + cv.y) + kv.y * pv.y
                + qv.z * (kv.z + cv.z) + kv.z * pv.z
                + qv.w * (kv.w + cv.w) + kv.w * pv.w;
#pragma unroll
        for (int o = 16; o > 0; o >>= 1) s += __shfl_xor_sync(0xffffffffu, s, o);
        if (lane == 0) sc[k] = s;
    }
    __syncthreads();

    float v0 = sc[tid], v1 = sc[tid + 256];
    float mx = fmaxf(v0, v1);
#pragma unroll
    for (int o = 16; o > 0; o >>= 1) mx = fmaxf(mx, __shfl_xor_sync(0xffffffffu, mx, o));
    if (lane == 0) red[w] = mx;
    __syncthreads();
    if (tid == 0) {
        float m2 = red[0];
#pragma unroll
        for (int i = 1; i < 8; i++) m2 = fmaxf(m2, red[i]);
        red[16] = m2;
    }
    __syncthreads();
    mx = red[16];
    float e0 = __expf(v0 - mx), e1 = __expf(v1 - mx);
    float s = e0 + e1;
#pragma unroll
    for (int o = 16; o > 0; o >>= 1) s += __shfl_xor_sync(0xffffffffu, s, o);
    __syncthreads();
    if (lane == 0) red[w] = s;
    __syncthreads();
    if (tid == 0) {
        float t = 0.f;
#pragma unroll
        for (int i = 0; i < 8; i++) t += red[i];
        red[16] = 1.f / t;
    }
    __syncthreads();
    float inv = red[16];
    float* srow = scores + (long)row * SS;
    srow[tid] = e0 * inv;
    srow[tid + 256] = e1 * inv;
}

// ctx2[b,q,h*128+d] = sum_k probs[z,q,k] * qkv_v[b,k,h*128+d]  + vb
__global__ void ctx_naive_kernel(const float* __restrict__ qkv, const float* __restrict__ scores,
                                 float* __restrict__ ctx2, const float* __restrict__ vb)
{
    __shared__ float ps[SS];
    int row = blockIdx.x;
    int z = row >> 9, q = row & 511;
    int b = z >> 3, h = z & 7;
    int tid = threadIdx.x;
    const float* srow = scores + (long)row * SS;
    for (int k = tid; k < SS; k += 128) ps[k] = srow[k];
    __syncthreads();
    int c = h * DHH + tid;
    const float* vp = qkv + (long)b * SS * (3 * HH) + 2 * HH + c;
    float acc = 0.f;
#pragma unroll 4
    for (int k = 0; k < SS; k++)
        acc = fmaf(ps[k], vp[(long)k * (3 * HH)], acc);
    acc += vb[c];
    ctx2[((long)(b * SS + q)) * HH + c] = acc;
}

// Persistent wavefront LSTM: 128 blocks (64 per dir, 8 units each), weights in smem.
// thread = (b = tid>>5, lane: ui = lane>>2, gate = lane&3); row r = gate*512 + u0 + ui.
__global__ void LSTMDisentangledAttention_15049565405471_kernel(
    const float* __restrict__ xw,
    const float* __restrict__ WhhF,
    const float* __restrict__ WhhR,
    float* __restrict__ out)
{
    extern __shared__ float sm[];
    float* Wsh = sm;              // [512][32] : Wsh[j*32+lane] = Whh[r(lane)][j]
    float* hs  = sm + HD * 32;    // [8][512]
    int tid = threadIdx.x, blk = blockIdx.x;
    int dir = blk >> 6;
    int u0  = (blk & 63) << 3;
    int b = tid >> 5, lane = tid & 31;
    int ui = lane >> 2, gate = lane & 3;
    int r = (gate << 9) + u0 + ui;
    const float* Whh = dir ? WhhR : WhhF;
    const float* xwd = xw + (long)dir * MM * G4;
    float* seq = g_hseq + (long)dir * 513 * (BB * HD);

    // Stage weight slice: Wsh[j*32 + l] = Whh[r(l)][j]   (one-time)
    for (int idx = tid; idx < HD * 32; idx += 256) {
        int j = idx >> 5, l = idx & 31;
        int rl = ((l & 3) << 9) + u0 + (l >> 2);
        Wsh[idx] = Whh[(long)rl * HD + j];
    }

    float c = 0.f;
    __syncthreads();

    for (int t = 0; t < SS; t++) {
        int sI = dir ? (SS - 1 - t) : t;
        const float* hrd = seq + (long)t * (BB * HD);
        // load h(t) into smem (slot t is complete: written before barrier t-1; slot 0 pre-zeroed)
        for (int idx = tid; idx < BB * HD; idx += 256)
            hs[idx] = hrd[idx];
        __syncthreads();

        float acc = xwd[((long)((b << 9) + sI)) * G4 + r];
        const float* hp = hs + (b << 9);
#pragma unroll 8
        for (int j = 0; j < HD; j++)
            acc = fmaf(Wsh[(j << 5) + lane], hp[j], acc);

        int base = lane & ~3;
        float vi = __shfl_sync(0xffffffffu, acc, base + 0);
        float vf = __shfl_sync(0xffffffffu, acc, base + 1);
        float vg = __shfl_sync(0xffffffffu, acc, base + 2);
        float vo = __shfl_sync(0xffffffffu, acc, base + 3);
        float ig = 1.f / (1.f + __expf(-vi));
        float fg = 1.f / (1.f + __expf(-vf));
        float gg = tanhf(vg);
        float og = 1.f / (1.f + __expf(-vo));
        c = fg * c + ig * gg;
        float hv = og * tanhf(c);
        if (gate == 0) {
            int u = u0 + ui;
            seq[(long)(t + 1) * (BB * HD) + (b << 9) + u] = hv;            // write-once slot t+1
            out[((long)((b << 9) + sI)) * HH + (dir << 9) + u] = hv;
        }
        // grid barrier: all h(t+1) writes visible before any block starts step t+1
        __threadfence();
        __syncthreads();
        if (tid == 0) {
            atomicAdd(&g_bar, 1u);
            unsigned target = (unsigned)(t + 1) * gridDim.x;
            while (*((volatile unsigned int*)&g_bar) < target) { __nanosleep(64); }
            __threadfence();
        }
        __syncthreads();
    }
}

extern "C" void kernel_launch(void* const* d_in, const int* in_sizes, int n_in,
                              void* d_out, int out_size)
{
    (void)in_sizes; (void)n_in; (void)out_size;
    const float* x       = (const float*)d_in[0];
    const float* pos_emb = (const float*)d_in[1];
    const float* emb_g   = (const float*)d_in[2];
    const float* emb_b   = (const float*)d_in[3];
    const float* in_w    = (const float*)d_in[4];
    const float* q_bias  = (const float*)d_in[5];
    const float* v_bias  = (const float*)d_in[6];
    const float* rel_emb = (const float*)d_in[7];
    const float* posk_w  = (const float*)d_in[8];
    const float* posq_w  = (const float*)d_in[9];
    const float* posq_b  = (const float*)d_in[10];
    const float* ao_w    = (const float*)d_in[11];
    const float* ao_b    = (const float*)d_in[12];
    const float* aln_g   = (const float*)d_in[13];
    const float* aln_b   = (const float*)d_in[14];
    const float* it_w    = (const float*)d_in[15];
    const float* it_b    = (const float*)d_in[16];
    const float* fo_w    = (const float*)d_in[17];
    const float* fo_b    = (const float*)d_in[18];
    const float* fln_g   = (const float*)d_in[19];
    const float* fln_b   = (const float*)d_in[20];
    const float* Wih_f   = (const float*)d_in[21];
    const float* Whh_f   = (const float*)d_in[22];
    const float* bih_f   = (const float*)d_in[23];
    const float* bhh_f   = (const float*)d_in[24];
    const float* Wih_r   = (const float*)d_in[25];
    const float* Whh_r   = (const float*)d_in[26];
    const float* bih_r   = (const float*)d_in[27];
    const float* bhh_r   = (const float*)d_in[28];
    float* out = (float*)d_out;

    float *h1, *qkv, *posk, *posq, *scores, *ctx2, *t1, *y, *h2, *h3, *xw;
    void  *barp, *seqp;
    cudaGetSymbolAddress((void**)&h1,     g_h1);
    cudaGetSymbolAddress((void**)&qkv,    g_qkv);
    cudaGetSymbolAddress((void**)&posk,   g_posk);
    cudaGetSymbolAddress((void**)&posq,   g_posq);
    cudaGetSymbolAddress((void**)&scores, g_scores);
    cudaGetSymbolAddress((void**)&ctx2,   g_ctx2);
    cudaGetSymbolAddress((void**)&t1,     g_t1);
    cudaGetSymbolAddress((void**)&y,      g_y);
    cudaGetSymbolAddress((void**)&h2,     g_h2);
    cudaGetSymbolAddress((void**)&h3,     g_h3);
    cudaGetSymbolAddress((void**)&xw,     g_xw);
    cudaGetSymbolAddress(&barp,           g_bar);
    cudaGetSymbolAddress(&seqp,           g_hseq);

    // 1. h1 = LN(x + pos_emb)
    add_pos_kernel<<<MM*HH/256, 256>>>(x, pos_emb, y);
    ln_kernel<<<MM, 256>>>(y, emb_g, emb_b, h1);
    // 2. qkv = h1 @ in_w^T
    sgemm_kernel<<<dim3(IN3/128, MM/128, 1), 256>>>(h1, in_w, qkv, MM, IN3, HH,
        0, 0, 0, 1.f, 0, 0, 0, 0, 0);
    // 3. pos tables (pos_q pre-scaled by 1/sqrt(384))
    sgemm_kernel<<<dim3(HH/128, R2/128, 1), 256>>>(rel_emb, posk_w, posk, R2, HH, HH,
        0, 0, 0, 1.f, 0, 0, 0, 0, 0);
    sgemm_kernel<<<dim3(HH/128, R2/128, 1), 256>>>(rel_emb, posq_w, posq, R2, HH, HH,
        posq_b, 0, 0, INV_SCALE, 0, 0, 0, 0, 0);
    // 4. fused scores + c2p + p2c + softmax
    attn_kernel<<<BB*NHH*SS, 256>>>(qkv, posk, posq, scores, q_bias);
    // 5. ctx directly from qkv
    ctx_naive_kernel<<<BB*NHH*SS, 128>>>(qkv, scores, ctx2, v_bias);
    // 6. attn out + residual + LN
    sgemm_kernel<<<dim3(HH/128, MM/128, 1), 256>>>(ctx2, ao_w, y, MM, HH, HH,
        ao_b, 0, h1, 1.f, 0, 0, 0, 0, (long)MM*HH);
    ln_kernel<<<MM, 256>>>(y, aln_g, aln_b, h2);
    // 7. FFN
    sgemm_kernel<<<dim3(IN3/128, MM/128, 1), 256>>>(h2, it_w, t1, MM, IN3, HH,
        it_b, 0, 0, 1.f, 1, 0, 0, 0, 0);
    sgemm_kernel<<<dim3(HH/128, MM/128, 1), 256>>>(t1, fo_w, y, MM, HH, IN3,
        fo_b, 0, h2, 1.f, 0, 0, 0, 0, (long)MM*HH);
    ln_kernel<<<MM, 256>>>(y, fln_g, fln_b, h3);
    // 8. LSTM input projections
    sgemm_kernel<<<dim3(G4/128, MM/128, 1), 256>>>(h3, Wih_f, xw, MM, G4, HH,
        bih_f, bhh_f, 0, 1.f, 0, 0, 0, 0, 0);
    sgemm_kernel<<<dim3(G4/128, MM/128, 1), 256>>>(h3, Wih_r, xw + (long)MM*G4, MM, G4, HH,
        bih_r, bhh_r, 0, 1.f, 0, 0, 0, 0, 0);
    // 9. persistent wavefront LSTM (reset barrier + zero h(0) both dirs)
    cudaMemsetAsync(barp, 0, sizeof(unsigned int), 0);
    cudaMemsetAsync(seqp, 0, sizeof(float) * BB * HD, 0);
    cudaMemsetAsync((char*)seqp + sizeof(float) * 513 * BB * HD, 0, sizeof(float) * BB * HD, 0);
    int smem = HD * 32 * 4 + BB * HD * 4;   // 64 KB + 16 KB
    cudaFuncSetAttribute(LSTMDisentangledAttention_15049565405471_kernel,
                         cudaFuncAttributeMaxDynamicSharedMemorySize, smem);
    LSTMDisentangledAttention_15049565405471_kernel<<<128, 256, smem>>>(xw, Whh_f, Whh_r, out);
}

// round 11
// speedup vs baseline: 37.9917x; 1.1459x over previous
#include <cuda_runtime.h>
#include <math.h>

#define BB   8
#define SS   512
#define HH   1024
#define NHH  8
#define DHH  128
#define MM   (BB*SS)
#define IN3  3072
#define R2   1024
#define HD   512
#define G4   2048
#define INV_SCALE 0.051031036307982884f  /* 1/sqrt(128*3) */

__device__ float g_h1[MM*HH];
__device__ float g_qkv[MM*3*HH];
__device__ float g_posk[R2*HH];
__device__ float g_posq[R2*HH];
__device__ float g_scores[BB*NHH*SS*SS];
__device__ float g_ctx2[MM*HH];
__device__ float g_t1[MM*IN3];
__device__ float g_y[MM*HH];
__device__ float g_h2[MM*HH];
__device__ float g_h3[MM*HH];
__device__ float g_xw[2*MM*G4];
__device__ float g_hseq[2*513*BB*HD];
__device__ unsigned int g_bar;

__device__ __forceinline__ unsigned tf32cvt(float x)
{
    unsigned r;
    asm("cvt.rna.tf32.f32 %0, %1;" : "=r"(r) : "f"(x));
    return r;
}

// Tensor-core GEMM: C = A[M,K] * B[N,K]^T via mma.sync m16n8k8 tf32.
// Block tile 128x128, 8 warps (2x4), warp tile 64x32. Fused epilogue.
__global__ void tgemm_kernel(const float* __restrict__ A, const float* __restrict__ Bw,
                             float* __restrict__ C, int Md, int Nd, int Kd,
                             const float* __restrict__ bias, const float* __restrict__ bias2,
                             const float* __restrict__ res, float scale, int act)
{
    __shared__ unsigned As[16][136];
    __shared__ unsigned Bs[16][136];
    int tid = threadIdx.x;
    int m0 = blockIdx.y << 7, n0 = blockIdx.x << 7;
    int warp = tid >> 5, lane = tid & 31;
    int wm = (warp >> 2) << 6;     // 0 or 64
    int wn = (warp & 3) << 5;      // 0,32,64,96
    int g = lane >> 2, tg = lane & 3;

    float c[4][4][4];
#pragma unroll
    for (int mt = 0; mt < 4; mt++)
#pragma unroll
        for (int nt = 0; nt < 4; nt++)
#pragma unroll
            for (int i = 0; i < 4; i++) c[mt][nt][i] = 0.f;

    for (int k0 = 0; k0 < Kd; k0 += 16) {
#pragma unroll
        for (int i = 0; i < 8; i++) {
            int l = tid + (i << 8);
            int rr = l >> 4, kk = l & 15;
            As[kk][rr] = tf32cvt(A[(long)(m0 + rr) * Kd + k0 + kk]);
            Bs[kk][rr] = tf32cvt(Bw[(long)(n0 + rr) * Kd + k0 + kk]);
        }
        __syncthreads();
#pragma unroll
        for (int kc = 0; kc < 2; kc++) {
            int kb = kc << 3;
            unsigned af[4][4], bf[4][2];
#pragma unroll
            for (int mt = 0; mt < 4; mt++) {
                int m = wm + (mt << 4);
                af[mt][0] = As[kb + tg][m + g];
                af[mt][1] = As[kb + tg][m + g + 8];
                af[mt][2] = As[kb + tg + 4][m + g];
                af[mt][3] = As[kb + tg + 4][m + g + 8];
            }
#pragma unroll
            for (int nt = 0; nt < 4; nt++) {
                int n = wn + (nt << 3);
                bf[nt][0] = Bs[kb + tg][n + g];
                bf[nt][1] = Bs[kb + tg + 4][n + g];
            }
#pragma unroll
            for (int mt = 0; mt < 4; mt++)
#pragma unroll
                for (int nt = 0; nt < 4; nt++) {
                    asm volatile(
                        "mma.sync.aligned.m16n8k8.row.col.f32.tf32.tf32.f32 "
                        "{%0,%1,%2,%3}, {%4,%5,%6,%7}, {%8,%9}, {%0,%1,%2,%3};"
                        : "+f"(c[mt][nt][0]), "+f"(c[mt][nt][1]),
                          "+f"(c[mt][nt][2]), "+f"(c[mt][nt][3])
                        : "r"(af[mt][0]), "r"(af[mt][1]), "r"(af[mt][2]), "r"(af[mt][3]),
                          "r"(bf[nt][0]), "r"(bf[nt][1]));
                }
        }
        __syncthreads();
    }

#pragma unroll
    for (int mt = 0; mt < 4; mt++) {
#pragma unroll
        for (int nt = 0; nt < 4; nt++) {
#pragma unroll
            for (int i = 0; i < 4; i++) {
                int m = m0 + wm + (mt << 4) + g + ((i >> 1) << 3);   // +8 for c2,c3
                int n = n0 + wn + (nt << 3) + (tg << 1) + (i & 1);
                float v = c[mt][nt][i];
                if (bias)  v += bias[n];
                if (bias2) v += bias2[n];
                if (res)   v += res[(long)m * Nd + n];
                v *= scale;
                if (act) v = 0.5f * v * (1.f + erff(v * 0.70710678118654752f));
                C[(long)m * Nd + n] = v;
            }
        }
    }
}

// y[b,s,c] = x[b,s,c] + pos[s,c]
__global__ void add_pos_kernel(const float* __restrict__ x, const float* __restrict__ pos,
                               float* __restrict__ y)
{
    long i = (long)blockIdx.x * blockDim.x + threadIdx.x;
    int c = (int)(i & 1023);
    int ms = (int)(i >> 10);
    int s = ms & 511;
    y[i] = x[i] + pos[(long)s * HH + c];
}

__global__ void ln_kernel(const float* __restrict__ in, const float* __restrict__ gw,
                          const float* __restrict__ bw, float* __restrict__ out)
{
    int row = blockIdx.x;
    const float* xp = in + (long)row * HH;
    int tid = threadIdx.x;
    float v[4]; float s = 0.f, sq = 0.f;
#pragma unroll
    for (int i = 0; i < 4; i++) {
        int c = tid + (i << 8);
        float t = xp[c];
        v[i] = t; s += t; sq += t * t;
    }
#pragma unroll
    for (int o = 16; o > 0; o >>= 1) {
        s  += __shfl_xor_sync(0xffffffffu, s, o);
        sq += __shfl_xor_sync(0xffffffffu, sq, o);
    }
    __shared__ float red[18];
    int w = tid >> 5, l = tid & 31;
    if (l == 0) { red[w] = s; red[8 + w] = sq; }
    __syncthreads();
    if (tid == 0) {
        float ts = 0.f, tq = 0.f;
#pragma unroll
        for (int i = 0; i < 8; i++) { ts += red[i]; tq += red[8 + i]; }
        float mean = ts * (1.f / HH);
        float var  = tq * (1.f / HH) - mean * mean;
        red[16] = mean; red[17] = rsqrtf(var + 1e-7f);
    }
    __syncthreads();
    float mean = red[16], rstd = red[17];
    float* op = out + (long)row * HH;
#pragma unroll
    for (int i = 0; i < 4; i++) {
        int c = tid + (i << 8);
        op[c] = (v[i] - mean) * rstd * gw[c] + bw[c];
    }
}

// Fused scores + c2p + p2c + softmax, coalesced warp-per-k.
__global__ void attn_kernel(const float* __restrict__ qkv, const float* __restrict__ posk,
                            const float* __restrict__ posq, float* __restrict__ scores,
                            const float* __restrict__ qb)
{
    int row = blockIdx.x;
    int z = row >> 9, q = row & 511;
    int b = z >> 3, h = z & 7;
    int tid = threadIdx.x;
    int w = tid >> 5, lane = tid & 31;
    __shared__ float qs[DHH];
    __shared__ float sc[SS];
    __shared__ float red[17];
    const float* qkvq = qkv + ((long)(b * SS + q)) * (3 * HH) + h * DHH;
    if (tid < DHH) qs[tid] = (qkvq[tid] + qb[h * DHH + tid]) * INV_SCALE;
    __syncthreads();
    float4 qv = ((const float4*)qs)[lane];

#pragma unroll 2
    for (int i = 0; i < 64; i++) {
        int k = (w << 6) + i;
        int rel = q - k + 512;
        float4 kv = ((const float4*)(qkv + ((long)(b * SS + k)) * (3 * HH) + HH + h * DHH))[lane];
        float4 cv = ((const float4*)(posk + (long)rel * HH + h * DHH))[lane];
        float4 pv = ((const float4*)(posq + (long)rel * HH + h * DHH))[lane];
        float s = qv.x * (kv.x + cv.x) + kv.x * pv.x
                + qv.y * (kv.y + cv.y) + kv.y * pv.y
                + qv.z * (kv.z + cv.z) + kv.z * pv.z
                + qv.w * (kv.w + cv.w) + kv.w * pv.w;
#pragma unroll
        for (int o = 16; o > 0; o >>= 1) s += __shfl_xor_sync(0xffffffffu, s, o);
        if (lane == 0) sc[k] = s;
    }
    __syncthreads();

    float v0 = sc[tid], v1 = sc[tid + 256];
    float mx = fmaxf(v0, v1);
#pragma unroll
    for (int o = 16; o > 0; o >>= 1) mx = fmaxf(mx, __shfl_xor_sync(0xffffffffu, mx, o));
    if (lane == 0) red[w] = mx;
    __syncthreads();
    if (tid == 0) {
        float m2 = red[0];
#pragma unroll
        for (int i = 1; i < 8; i++) m2 = fmaxf(m2, red[i]);
        red[16] = m2;
    }
    __syncthreads();
    mx = red[16];
    float e0 = __expf(v0 - mx), e1 = __expf(v1 - mx);
    float s = e0 + e1;
#pragma unroll
    for (int o = 16; o > 0; o >>= 1) s += __shfl_xor_sync(0xffffffffu, s, o);
    __syncthreads();
    if (lane == 0) red[w] = s;
    __syncthreads();
    if (tid == 0) {
        float t = 0.f;
#pragma unroll
        for (int i = 0; i < 8; i++) t += red[i];
        red[16] = 1.f / t;
    }
    __syncthreads();
    float inv = red[16];
    float* srow = scores + (long)row * SS;
    srow[tid] = e0 * inv;
    srow[tid + 256] = e1 * inv;
}

// ctx2[b,q,h*128+d] = sum_k probs[z,q,k] * qkv_v[b,k,h*128+d]  + vb
__global__ void ctx_naive_kernel(const float* __restrict__ qkv, const float* __restrict__ scores,
                                 float* __restrict__ ctx2, const float* __restrict__ vb)
{
    __shared__ float ps[SS];
    int row = blockIdx.x;
    int z = row >> 9, q = row & 511;
    int b = z >> 3, h = z & 7;
    int tid = threadIdx.x;
    const float* srow = scores + (long)row * SS;
    for (int k = tid; k < SS; k += 128) ps[k] = srow[k];
    __syncthreads();
    int c = h * DHH + tid;
    const float* vp = qkv + (long)b * SS * (3 * HH) + 2 * HH + c;
    float acc = 0.f;
#pragma unroll 4
    for (int k = 0; k < SS; k++)
        acc = fmaf(ps[k], vp[(long)k * (3 * HH)], acc);
    acc += vb[c];
    ctx2[((long)(b * SS + q)) * HH + c] = acc;
}

// Persistent wavefront LSTM: 128 blocks, weights in smem, write-once h sequence.
__global__ void LSTMDisentangledAttention_15049565405471_kernel(
    const float* __restrict__ xw,
    const float* __restrict__ WhhF,
    const float* __restrict__ WhhR,
    float* __restrict__ out)
{
    extern __shared__ float sm[];
    float* Wsh = sm;              // [512][32]
    float* hs  = sm + HD * 32;    // [8][512]
    int tid = threadIdx.x, blk = blockIdx.x;
    int dir = blk >> 6;
    int u0  = (blk & 63) << 3;
    int b = tid >> 5, lane = tid & 31;
    int ui = lane >> 2, gate = lane & 3;
    int r = (gate << 9) + u0 + ui;
    const float* Whh = dir ? WhhR : WhhF;
    const float* xwd = xw + (long)dir * MM * G4;
    float* seq = g_hseq + (long)dir * 513 * (BB * HD);

    for (int idx = tid; idx < HD * 32; idx += 256) {
        int j = idx >> 5, l = idx & 31;
        int rl = ((l & 3) << 9) + u0 + (l >> 2);
        Wsh[idx] = Whh[(long)rl * HD + j];
    }

    float c = 0.f;
    __syncthreads();

    for (int t = 0; t < SS; t++) {
        int sI = dir ? (SS - 1 - t) : t;
        const float* hrd = seq + (long)t * (BB * HD);
        for (int idx = tid; idx < BB * HD; idx += 256)
            hs[idx] = hrd[idx];
        __syncthreads();

        float acc = xwd[((long)((b << 9) + sI)) * G4 + r];
        const float* hp = hs + (b << 9);
#pragma unroll 8
        for (int j = 0; j < HD; j++)
            acc = fmaf(Wsh[(j << 5) + lane], hp[j], acc);

        int base = lane & ~3;
        float vi = __shfl_sync(0xffffffffu, acc, base + 0);
        float vf = __shfl_sync(0xffffffffu, acc, base + 1);
        float vg = __shfl_sync(0xffffffffu, acc, base + 2);
        float vo = __shfl_sync(0xffffffffu, acc, base + 3);
        float ig = 1.f / (1.f + __expf(-vi));
        float fg = 1.f / (1.f + __expf(-vf));
        float gg = tanhf(vg);
        float og = 1.f / (1.f + __expf(-vo));
        c = fg * c + ig * gg;
        float hv = og * tanhf(c);
        if (gate == 0) {
            int u = u0 + ui;
            seq[(long)(t + 1) * (BB * HD) + (b << 9) + u] = hv;
            out[((long)((b << 9) + sI)) * HH + (dir << 9) + u] = hv;
        }
        __threadfence();
        __syncthreads();
        if (tid == 0) {
            atomicAdd(&g_bar, 1u);
            unsigned target = (unsigned)(t + 1) * gridDim.x;
            while (*((volatile unsigned int*)&g_bar) < target) { __nanosleep(64); }
            __threadfence();
        }
        __syncthreads();
    }
}

extern "C" void kernel_launch(void* const* d_in, const int* in_sizes, int n_in,
                              void* d_out, int out_size)
{
    (void)in_sizes; (void)n_in; (void)out_size;
    const float* x       = (const float*)d_in[0];
    const float* pos_emb = (const float*)d_in[1];
    const float* emb_g   = (const float*)d_in[2];
    const float* emb_b   = (const float*)d_in[3];
    const float* in_w    = (const float*)d_in[4];
    const float* q_bias  = (const float*)d_in[5];
    const float* v_bias  = (const float*)d_in[6];
    const float* rel_emb = (const float*)d_in[7];
    const float* posk_w  = (const float*)d_in[8];
    const float* posq_w  = (const float*)d_in[9];
    const float* posq_b  = (const float*)d_in[10];
    const float* ao_w    = (const float*)d_in[11];
    const float* ao_b    = (const float*)d_in[12];
    const float* aln_g   = (const float*)d_in[13];
    const float* aln_b   = (const float*)d_in[14];
    const float* it_w    = (const float*)d_in[15];
    const float* it_b    = (const float*)d_in[16];
    const float* fo_w    = (const float*)d_in[17];
    const float* fo_b    = (const float*)d_in[18];
    const float* fln_g   = (const float*)d_in[19];
    const float* fln_b   = (const float*)d_in[20];
    const float* Wih_f   = (const float*)d_in[21];
    const float* Whh_f   = (const float*)d_in[22];
    const float* bih_f   = (const float*)d_in[23];
    const float* bhh_f   = (const float*)d_in[24];
    const float* Wih_r   = (const float*)d_in[25];
    const float* Whh_r   = (const float*)d_in[26];
    const float* bih_r   = (const float*)d_in[27];
    const float* bhh_r   = (const float*)d_in[28];
    float* out = (float*)d_out;

    float *h1, *qkv, *posk, *posq, *scores, *ctx2, *t1, *y, *h2, *h3, *xw;
    void  *barp, *seqp;
    cudaGetSymbolAddress((void**)&h1,     g_h1);
    cudaGetSymbolAddress((void**)&qkv,    g_qkv);
    cudaGetSymbolAddress((void**)&posk,   g_posk);
    cudaGetSymbolAddress((void**)&posq,   g_posq);
    cudaGetSymbolAddress((void**)&scores, g_scores);
    cudaGetSymbolAddress((void**)&ctx2,   g_ctx2);
    cudaGetSymbolAddress((void**)&t1,     g_t1);
    cudaGetSymbolAddress((void**)&y,      g_y);
    cudaGetSymbolAddress((void**)&h2,     g_h2);
    cudaGetSymbolAddress((void**)&h3,     g_h3);
    cudaGetSymbolAddress((void**)&xw,     g_xw);
    cudaGetSymbolAddress(&barp,           g_bar);
    cudaGetSymbolAddress(&seqp,           g_hseq);

    // 1. h1 = LN(x + pos_emb)
    add_pos_kernel<<<MM*HH/256, 256>>>(x, pos_emb, y);
    ln_kernel<<<MM, 256>>>(y, emb_g, emb_b, h1);
    // 2. qkv = h1 @ in_w^T   (tensor core)
    tgemm_kernel<<<dim3(IN3/128, MM/128), 256>>>(h1, in_w, qkv, MM, IN3, HH,
        0, 0, 0, 1.f, 0);
    // 3. pos tables (pos_q pre-scaled)
    tgemm_kernel<<<dim3(HH/128, R2/128), 256>>>(rel_emb, posk_w, posk, R2, HH, HH,
        0, 0, 0, 1.f, 0);
    tgemm_kernel<<<dim3(HH/128, R2/128), 256>>>(rel_emb, posq_w, posq, R2, HH, HH,
        posq_b, 0, 0, INV_SCALE, 0);
    // 4. fused scores + c2p + p2c + softmax
    attn_kernel<<<BB*NHH*SS, 256>>>(qkv, posk, posq, scores, q_bias);
    // 5. ctx directly from qkv
    ctx_naive_kernel<<<BB*NHH*SS, 128>>>(qkv, scores, ctx2, v_bias);
    // 6. attn out + residual + LN
    tgemm_kernel<<<dim3(HH/128, MM/128), 256>>>(ctx2, ao_w, y, MM, HH, HH,
        ao_b, 0, h1, 1.f, 0);
    ln_kernel<<<MM, 256>>>(y, aln_g, aln_b, h2);
    // 7. FFN
    tgemm_kernel<<<dim3(IN3/128, MM/128), 256>>>(h2, it_w, t1, MM, IN3, HH,
        it_b, 0, 0, 1.f, 1);
    tgemm_kernel<<<dim3(HH/128, MM/128), 256>>>(t1, fo_w, y, MM, HH, IN3,
        fo_b, 0, h2, 1.f, 0);
    ln_kernel<<<MM, 256>>>(y, fln_g, fln_b, h3);
    // 8. LSTM input projections
    tgemm_kernel<<<dim3(G4/128, MM/128), 256>>>(h3, Wih_f, xw, MM, G4, HH,
        bih_f, bhh_f, 0, 1.f, 0);
    tgemm_kernel<<<dim3(G4/128, MM/128), 256>>>(h3, Wih_r, xw + (long)MM*G4, MM, G4, HH,
        bih_r, bhh_r, 0, 1.f, 0);
    // 9. persistent wavefront LSTM
    cudaMemsetAsync(barp, 0, sizeof(unsigned int), 0);
    cudaMemsetAsync(seqp, 0, sizeof(float) * BB * HD, 0);
    cudaMemsetAsync((char*)seqp + sizeof(float) * 513 * BB * HD, 0, sizeof(float) * BB * HD, 0);
    int smem = HD * 32 * 4 + BB * HD * 4;
    cudaFuncSetAttribute(LSTMDisentangledAttention_15049565405471_kernel,
                         cudaFuncAttributeMaxDynamicSharedMemorySize, smem);
    LSTMDisentangledAttention_15049565405471_kernel<<<128, 256, smem>>>(xw, Whh_f, Whh_r, out);
}

// round 12
// speedup vs baseline: 44.7286x; 1.1773x over previous
#include <cuda_runtime.h>
#include <math.h>

#define BB   8
#define SS   512
#define HH   1024
#define NHH  8
#define DHH  128
#define MM   (BB*SS)
#define IN3  3072
#define R2   1024
#define HD   512
#define G4   2048
#define INV_SCALE 0.051031036307982884f  /* 1/sqrt(128*3) */
#define TP   36                          /* smem row pitch (floats): banks 4g+tg, conflict-free */

__device__ float g_h1[MM*HH];
__device__ float g_qkv[MM*3*HH];
__device__ float g_posk[R2*HH];
__device__ float g_posq[R2*HH];
__device__ float g_scores[BB*NHH*SS*SS];
__device__ float g_ctx2[MM*HH];
__device__ float g_t1[MM*IN3];
__device__ float g_y[MM*HH];
__device__ float g_h2[MM*HH];
__device__ float g_h3[MM*HH];
__device__ float g_xw[2*MM*G4];
__device__ float g_hseq[2*513*BB*HD];
__device__ unsigned int g_bar2[2];

__device__ __forceinline__ unsigned tf32cvt(float x)
{
    unsigned r;
    asm("cvt.rna.tf32.f32 %0, %1;" : "=r"(r) : "f"(x));
    return r;
}

// Tensor-core GEMM: C = A[M,K]*B[N,K]^T, mma m16n8k8 tf32.
// 128x128 block tile, 8 warps (2x4), warp 64x32. K-tile 32, cp.async double buffer.
__global__ void tgemm_kernel(const float* __restrict__ A, const float* __restrict__ Bw,
                             float* __restrict__ C, int Md, int Nd, int Kd,
                             const float* __restrict__ bias, const float* __restrict__ bias2,
                             const float* __restrict__ res, float scale, int act)
{
    extern __shared__ float sm[];
    float* Asm = sm;                       // [2][128][TP]
    float* Bsm = sm + 2 * 128 * TP;        // [2][128][TP]
    int tid = threadIdx.x;
    int m0 = blockIdx.y << 7, n0 = blockIdx.x << 7;
    int warp = tid >> 5, lane = tid & 31;
    int wm = (warp >> 2) << 6;             // 0 or 64
    int wn = (warp & 3) << 5;              // 0,32,64,96
    int g = lane >> 2, tg = lane & 3;

    float c[4][4][4];
#pragma unroll
    for (int mt = 0; mt < 4; mt++)
#pragma unroll
        for (int nt = 0; nt < 4; nt++)
#pragma unroll
            for (int i = 0; i < 4; i++) c[mt][nt][i] = 0.f;

    auto load_tile = [&](int st, int k0) {
#pragma unroll
        for (int i = 0; i < 4; i++) {
            int ch = tid + (i << 8);
            int row = ch >> 3, c4 = (ch & 7) << 2;
            unsigned sa = (unsigned)__cvta_generic_to_shared(&Asm[((st << 7) + row) * TP + c4]);
            asm volatile("cp.async.cg.shared.global [%0], [%1], 16;"
                         :: "r"(sa), "l"(A + (long)(m0 + row) * Kd + k0 + c4));
            unsigned sb = (unsigned)__cvta_generic_to_shared(&Bsm[((st << 7) + row) * TP + c4]);
            asm volatile("cp.async.cg.shared.global [%0], [%1], 16;"
                         :: "r"(sb), "l"(Bw + (long)(n0 + row) * Kd + k0 + c4));
        }
        asm volatile("cp.async.commit_group;");
    };

    int nk = Kd >> 5;
    load_tile(0, 0);
    for (int kt = 0; kt < nk; kt++) {
        asm volatile("cp.async.wait_group 0;");
        __syncthreads();
        if (kt + 1 < nk) load_tile((kt + 1) & 1, (kt + 1) << 5);
        const float* As = Asm + ((long)(kt & 1) << 7) * TP;
        const float* Bs = Bsm + ((long)(kt & 1) << 7) * TP;
#pragma unroll
        for (int kc = 0; kc < 4; kc++) {
            int kb = kc << 3;
            unsigned af[4][4], bf[4][2];
#pragma unroll
            for (int mt = 0; mt < 4; mt++) {
                int m = wm + (mt << 4);
                af[mt][0] = tf32cvt(As[(m + g) * TP + kb + tg]);
                af[mt][1] = tf32cvt(As[(m + g + 8) * TP + kb + tg]);
                af[mt][2] = tf32cvt(As[(m + g) * TP + kb + tg + 4]);
                af[mt][3] = tf32cvt(As[(m + g + 8) * TP + kb + tg + 4]);
            }
#pragma unroll
            for (int nt = 0; nt < 4; nt++) {
                int n = wn + (nt << 3);
                bf[nt][0] = tf32cvt(Bs[(n + g) * TP + kb + tg]);
                bf[nt][1] = tf32cvt(Bs[(n + g) * TP + kb + tg + 4]);
            }
#pragma unroll
            for (int mt = 0; mt < 4; mt++)
#pragma unroll
                for (int nt = 0; nt < 4; nt++) {
                    asm volatile(
                        "mma.sync.aligned.m16n8k8.row.col.f32.tf32.tf32.f32 "
                        "{%0,%1,%2,%3}, {%4,%5,%6,%7}, {%8,%9}, {%0,%1,%2,%3};"
                        : "+f"(c[mt][nt][0]), "+f"(c[mt][nt][1]),
                          "+f"(c[mt][nt][2]), "+f"(c[mt][nt][3])
                        : "r"(af[mt][0]), "r"(af[mt][1]), "r"(af[mt][2]), "r"(af[mt][3]),
                          "r"(bf[nt][0]), "r"(bf[nt][1]));
                }
        }
    }

#pragma unroll
    for (int mt = 0; mt < 4; mt++) {
#pragma unroll
        for (int nt = 0; nt < 4; nt++) {
#pragma unroll
            for (int i = 0; i < 4; i++) {
                int m = m0 + wm + (mt << 4) + g + ((i >> 1) << 3);
                int n = n0 + wn + (nt << 3) + (tg << 1) + (i & 1);
                float v = c[mt][nt][i];
                if (bias)  v += bias[n];
                if (bias2) v += bias2[n];
                if (res)   v += res[(long)m * Nd + n];
                v *= scale;
                if (act) v = 0.5f * v * (1.f + erff(v * 0.70710678118654752f));
                C[(long)m * Nd + n] = v;
            }
        }
    }
}

// y[b,s,c] = x[b,s,c] + pos[s,c]
__global__ void add_pos_kernel(const float* __restrict__ x, const float* __restrict__ pos,
                               float* __restrict__ y)
{
    long i = (long)blockIdx.x * blockDim.x + threadIdx.x;
    int c = (int)(i & 1023);
    int ms = (int)(i >> 10);
    int s = ms & 511;
    y[i] = x[i] + pos[(long)s * HH + c];
}

__global__ void ln_kernel(const float* __restrict__ in, const float* __restrict__ gw,
                          const float* __restrict__ bw, float* __restrict__ out)
{
    int row = blockIdx.x;
    const float* xp = in + (long)row * HH;
    int tid = threadIdx.x;
    float v[4]; float s = 0.f, sq = 0.f;
#pragma unroll
    for (int i = 0; i < 4; i++) {
        int c = tid + (i << 8);
        float t = xp[c];
        v[i] = t; s += t; sq += t * t;
    }
#pragma unroll
    for (int o = 16; o > 0; o >>= 1) {
        s  += __shfl_xor_sync(0xffffffffu, s, o);
        sq += __shfl_xor_sync(0xffffffffu, sq, o);
    }
    __shared__ float red[18];
    int w = tid >> 5, l = tid & 31;
    if (l == 0) { red[w] = s; red[8 + w] = sq; }
    __syncthreads();
    if (tid == 0) {
        float ts = 0.f, tq = 0.f;
#pragma unroll
        for (int i = 0; i < 8; i++) { ts += red[i]; tq += red[8 + i]; }
        float mean = ts * (1.f / HH);
        float var  = tq * (1.f / HH) - mean * mean;
        red[16] = mean; red[17] = rsqrtf(var + 1e-7f);
    }
    __syncthreads();
    float mean = red[16], rstd = red[17];
    float* op = out + (long)row * HH;
#pragma unroll
    for (int i = 0; i < 4; i++) {
        int c = tid + (i << 8);
        op[c] = (v[i] - mean) * rstd * gw[c] + bw[c];
    }
}

// Fused scores + c2p + p2c + softmax, coalesced warp-per-k.
__global__ void attn_kernel(const float* __restrict__ qkv, const float* __restrict__ posk,
                            const float* __restrict__ posq, float* __restrict__ scores,
                            const float* __restrict__ qb)
{
    int row = blockIdx.x;
    int z = row >> 9, q = row & 511;
    int b = z >> 3, h = z & 7;
    int tid = threadIdx.x;
    int w = tid >> 5, lane = tid & 31;
    __shared__ float qs[DHH];
    __shared__ float sc[SS];
    __shared__ float red[17];
    const float* qkvq = qkv + ((long)(b * SS + q)) * (3 * HH) + h * DHH;
    if (tid < DHH) qs[tid] = (qkvq[tid] + qb[h * DHH + tid]) * INV_SCALE;
    __syncthreads();
    float4 qv = ((const float4*)qs)[lane];

#pragma unroll 2
    for (int i = 0; i < 64; i++) {
        int k = (w << 6) + i;
        int rel = q - k + 512;
        float4 kv = ((const float4*)(qkv + ((long)(b * SS + k)) * (3 * HH) + HH + h * DHH))[lane];
        float4 cv = ((const float4*)(posk + (long)rel * HH + h * DHH))[lane];
        float4 pv = ((const float4*)(posq + (long)rel * HH + h * DHH))[lane];
        float s = qv.x * (kv.x + cv.x) + kv.x * pv.x
                + qv.y * (kv.y + cv.y) + kv.y * pv.y
                + qv.z * (kv.z + cv.z) + kv.z * pv.z
                + qv.w * (kv.w + cv.w) + kv.w * pv.w;
#pragma unroll
        for (int o = 16; o > 0; o >>= 1) s += __shfl_xor_sync(0xffffffffu, s, o);
        if (lane == 0) sc[k] = s;
    }
    __syncthreads();

    float v0 = sc[tid], v1 = sc[tid + 256];
    float mx = fmaxf(v0, v1);
#pragma unroll
    for (int o = 16; o > 0; o >>= 1) mx = fmaxf(mx, __shfl_xor_sync(0xffffffffu, mx, o));
    if (lane == 0) red[w] = mx;
    __syncthreads();
    if (tid == 0) {
        float m2 = red[0];
#pragma unroll
        for (int i = 1; i < 8; i++) m2 = fmaxf(m2, red[i]);
        red[16] = m2;
    }
    __syncthreads();
    mx = red[16];
    float e0 = __expf(v0 - mx), e1 = __expf(v1 - mx);
    float s = e0 + e1;
#pragma unroll
    for (int o = 16; o > 0; o >>= 1) s += __shfl_xor_sync(0xffffffffu, s, o);
    __syncthreads();
    if (lane == 0) red[w] = s;
    __syncthreads();
    if (tid == 0) {
        float t = 0.f;
#pragma unroll
        for (int i = 0; i < 8; i++) t += red[i];
        red[16] = 1.f / t;
    }
    __syncthreads();
    float inv = red[16];
    float* srow = scores + (long)row * SS;
    srow[tid] = e0 * inv;
    srow[tid + 256] = e1 * inv;
}

// ctx2[b,q,h*128+d] = sum_k probs[z,q,k] * qkv_v[b,k,h*128+d]  + vb
__global__ void ctx_naive_kernel(const float* __restrict__ qkv, const float* __restrict__ scores,
                                 float* __restrict__ ctx2, const float* __restrict__ vb)
{
    __shared__ float ps[SS];
    int row = blockIdx.x;
    int z = row >> 9, q = row & 511;
    int b = z >> 3, h = z & 7;
    int tid = threadIdx.x;
    const float* srow = scores + (long)row * SS;
    for (int k = tid; k < SS; k += 128) ps[k] = srow[k];
    __syncthreads();
    int c = h * DHH + tid;
    const float* vp = qkv + (long)b * SS * (3 * HH) + 2 * HH + c;
    float acc = 0.f;
#pragma unroll 4
    for (int k = 0; k < SS; k++)
        acc = fmaf(ps[k], vp[(long)k * (3 * HH)], acc);
    acc += vb[c];
    ctx2[((long)(b * SS + q)) * HH + c] = acc;
}

// Persistent wavefront LSTM: 128 blocks, per-direction barriers (64 arrivals).
__global__ void LSTMDisentangledAttention_15049565405471_kernel(
    const float* __restrict__ xw,
    const float* __restrict__ WhhF,
    const float* __restrict__ WhhR,
    float* __restrict__ out)
{
    extern __shared__ float sm[];
    float* Wsh = sm;              // [512][32]
    float* hs  = sm + HD * 32;    // [8][512]
    int tid = threadIdx.x, blk = blockIdx.x;
    int dir = blk >> 6;
    int u0  = (blk & 63) << 3;
    int b = tid >> 5, lane = tid & 31;
    int ui = lane >> 2, gate = lane & 3;
    int r = (gate << 9) + u0 + ui;
    const float* Whh = dir ? WhhR : WhhF;
    const float* xwd = xw + (long)dir * MM * G4;
    float* seq = g_hseq + (long)dir * 513 * (BB * HD);
    unsigned int* bar = &g_bar2[dir];

    for (int idx = tid; idx < HD * 32; idx += 256) {
        int j = idx >> 5, l = idx & 31;
        int rl = ((l & 3) << 9) + u0 + (l >> 2);
        Wsh[idx] = Whh[(long)rl * HD + j];
    }

    float c = 0.f;
    __syncthreads();

    for (int t = 0; t < SS; t++) {
        int sI = dir ? (SS - 1 - t) : t;
        const float* hrd = seq + (long)t * (BB * HD);
        for (int idx = tid; idx < BB * HD; idx += 256)
            hs[idx] = hrd[idx];
        __syncthreads();

        float acc = xwd[((long)((b << 9) + sI)) * G4 + r];
        const float* hp = hs + (b << 9);
#pragma unroll 8
        for (int j = 0; j < HD; j++)
            acc = fmaf(Wsh[(j << 5) + lane], hp[j], acc);

        int base = lane & ~3;
        float vi = __shfl_sync(0xffffffffu, acc, base + 0);
        float vf = __shfl_sync(0xffffffffu, acc, base + 1);
        float vg = __shfl_sync(0xffffffffu, acc, base + 2);
        float vo = __shfl_sync(0xffffffffu, acc, base + 3);
        float ig = 1.f / (1.f + __expf(-vi));
        float fg = 1.f / (1.f + __expf(-vf));
        float gg = tanhf(vg);
        float og = 1.f / (1.f + __expf(-vo));
        c = fg * c + ig * gg;
        float hv = og * tanhf(c);
        if (gate == 0) {
            int u = u0 + ui;
            seq[(long)(t + 1) * (BB * HD) + (b << 9) + u] = hv;
            out[((long)((b << 9) + sI)) * HH + (dir << 9) + u] = hv;
        }
        __threadfence();
        __syncthreads();
        if (tid == 0) {
            atomicAdd(bar, 1u);
            unsigned target = (unsigned)(t + 1) * 64u;
            while (*((volatile unsigned int*)bar) < target) { }
            __threadfence();
        }
        __syncthreads();
    }
}

extern "C" void kernel_launch(void* const* d_in, const int* in_sizes, int n_in,
                              void* d_out, int out_size)
{
    (void)in_sizes; (void)n_in; (void)out_size;
    const float* x       = (const float*)d_in[0];
    const float* pos_emb = (const float*)d_in[1];
    const float* emb_g   = (const float*)d_in[2];
    const float* emb_b   = (const float*)d_in[3];
    const float* in_w    = (const float*)d_in[4];
    const float* q_bias  = (const float*)d_in[5];
    const float* v_bias  = (const float*)d_in[6];
    const float* rel_emb = (const float*)d_in[7];
    const float* posk_w  = (const float*)d_in[8];
    const float* posq_w  = (const float*)d_in[9];
    const float* posq_b  = (const float*)d_in[10];
    const float* ao_w    = (const float*)d_in[11];
    const float* ao_b    = (const float*)d_in[12];
    const float* aln_g   = (const float*)d_in[13];
    const float* aln_b   = (const float*)d_in[14];
    const float* it_w    = (const float*)d_in[15];
    const float* it_b    = (const float*)d_in[16];
    const float* fo_w    = (const float*)d_in[17];
    const float* fo_b    = (const float*)d_in[18];
    const float* fln_g   = (const float*)d_in[19];
    const float* fln_b   = (const float*)d_in[20];
    const float* Wih_f   = (const float*)d_in[21];
    const float* Whh_f   = (const float*)d_in[22];
    const float* bih_f   = (const float*)d_in[23];
    const float* bhh_f   = (const float*)d_in[24];
    const float* Wih_r   = (const float*)d_in[25];
    const float* Whh_r   = (const float*)d_in[26];
    const float* bih_r   = (const float*)d_in[27];
    const float* bhh_r   = (const float*)d_in[28];
    float* out = (float*)d_out;

    float *h1, *qkv, *posk, *posq, *scores, *ctx2, *t1, *y, *h2, *h3, *xw;
    void  *barp, *seqp;
    cudaGetSymbolAddress((void**)&h1,     g_h1);
    cudaGetSymbolAddress((void**)&qkv,    g_qkv);
    cudaGetSymbolAddress((void**)&posk,   g_posk);
    cudaGetSymbolAddress((void**)&posq,   g_posq);
    cudaGetSymbolAddress((void**)&scores, g_scores);
    cudaGetSymbolAddress((void**)&ctx2,   g_ctx2);
    cudaGetSymbolAddress((void**)&t1,     g_t1);
    cudaGetSymbolAddress((void**)&y,      g_y);
    cudaGetSymbolAddress((void**)&h2,     g_h2);
    cudaGetSymbolAddress((void**)&h3,     g_h3);
    cudaGetSymbolAddress((void**)&xw,     g_xw);
    cudaGetSymbolAddress(&barp,           g_bar2);
    cudaGetSymbolAddress(&seqp,           g_hseq);

    int gsmem = 2 * 2 * 128 * TP * 4;   // 73728 B
    cudaFuncSetAttribute(tgemm_kernel, cudaFuncAttributeMaxDynamicSharedMemorySize, gsmem);

    // 1. h1 = LN(x + pos_emb)
    add_pos_kernel<<<MM*HH/256, 256>>>(x, pos_emb, y);
    ln_kernel<<<MM, 256>>>(y, emb_g, emb_b, h1);
    // 2. qkv = h1 @ in_w^T
    tgemm_kernel<<<dim3(IN3/128, MM/128), 256, gsmem>>>(h1, in_w, qkv, MM, IN3, HH,
        0, 0, 0, 1.f, 0);
    // 3. pos tables (pos_q pre-scaled)
    tgemm_kernel<<<dim3(HH/128, R2/128), 256, gsmem>>>(rel_emb, posk_w, posk, R2, HH, HH,
        0, 0, 0, 1.f, 0);
    tgemm_kernel<<<dim3(HH/128, R2/128), 256, gsmem>>>(rel_emb, posq_w, posq, R2, HH, HH,
        posq_b, 0, 0, INV_SCALE, 0);
    // 4. fused scores + c2p + p2c + softmax
    attn_kernel<<<BB*NHH*SS, 256>>>(qkv, posk, posq, scores, q_bias);
    // 5. ctx directly from qkv
    ctx_naive_kernel<<<BB*NHH*SS, 128>>>(qkv, scores, ctx2, v_bias);
    // 6. attn out + residual + LN
    tgemm_kernel<<<dim3(HH/128, MM/128), 256, gsmem>>>(ctx2, ao_w, y, MM, HH, HH,
        ao_b, 0, h1, 1.f, 0);
    ln_kernel<<<MM, 256>>>(y, aln_g, aln_b, h2);
    // 7. FFN
    tgemm_kernel<<<dim3(IN3/128, MM/128), 256, gsmem>>>(h2, it_w, t1, MM, IN3, HH,
        it_b, 0, 0, 1.f, 1);
    tgemm_kernel<<<dim3(HH/128, MM/128), 256, gsmem>>>(t1, fo_w, y, MM, HH, IN3,
        fo_b, 0, h2, 1.f, 0);
    ln_kernel<<<MM, 256>>>(y, fln_g, fln_b, h3);
    // 8. LSTM input projections
    tgemm_kernel<<<dim3(G4/128, MM/128), 256, gsmem>>>(h3, Wih_f, xw, MM, G4, HH,
        bih_f, bhh_f, 0, 1.f, 0);
    tgemm_kernel<<<dim3(G4/128, MM/128), 256, gsmem>>>(h3, Wih_r, xw + (long)MM*G4, MM, G4, HH,
        bih_r, bhh_r, 0, 1.f, 0);
    // 9. persistent wavefront LSTM (per-direction barriers)
    cudaMemsetAsync(barp, 0, 2 * sizeof(unsigned int), 0);
    cudaMemsetAsync(seqp, 0, sizeof(float) * BB * HD, 0);
    cudaMemsetAsync((char*)seqp + sizeof(float) * 513 * BB * HD, 0, sizeof(float) * BB * HD, 0);
    int lsmem = HD * 32 * 4 + BB * HD * 4;
    cudaFuncSetAttribute(LSTMDisentangledAttention_15049565405471_kernel,
                         cudaFuncAttributeMaxDynamicSharedMemorySize, lsmem);
    LSTMDisentangledAttention_15049565405471_kernel<<<128, 256, lsmem>>>(xw, Whh_f, Whh_r, out);
}

// round 13
// speedup vs baseline: 45.2432x; 1.0115x over previous
#include <cuda_runtime.h>
#include <math.h>

#define BB   8
#define SS   512
#define HH   1024
#define NHH  8
#define DHH  128
#define MM   (BB*SS)
#define IN3  3072
#define R2   1024
#define HD   512
#define G4   2048
#define INV_SCALE 0.051031036307982884f  /* 1/sqrt(128*3) */
#define TP2  20                          /* smem row pitch (floats) for K-tile 16 */

__device__ float g_h1[MM*HH];
__device__ float g_qkv[MM*3*HH];
__device__ float g_posk[R2*HH];
__device__ float g_posq[R2*HH];
__device__ float g_scores[BB*NHH*SS*SS];
__device__ float g_ctx2[MM*HH];
__device__ float g_t1[MM*IN3];
__device__ float g_y[MM*HH];
__device__ float g_h2[MM*HH];
__device__ float g_h3[MM*HH];
__device__ float g_xw[2*MM*G4];
__device__ float g_hseq[2*513*BB*HD];
__device__ unsigned int g_bar2[2];

__device__ __forceinline__ unsigned tf32cvt(float x)
{
    unsigned r;
    asm("cvt.rna.tf32.f32 %0, %1;" : "=r"(r) : "f"(x));
    return r;
}

// Tensor-core GEMM: C = A[M,K]*B[N,K]^T, mma m16n8k8 tf32.
// 128x128 block tile, 8 warps (2x4), warp 64x32. K-tile 16, cp.async double buffer,
// 2 blocks/SM.
__global__ void __launch_bounds__(256, 2)
tgemm_kernel(const float* __restrict__ A, const float* __restrict__ Bw,
             float* __restrict__ C, int Md, int Nd, int Kd,
             const float* __restrict__ bias, const float* __restrict__ bias2,
             const float* __restrict__ res, float scale, int act)
{
    extern __shared__ float sm[];
    float* Asm = sm;                       // [2][128][TP2]
    float* Bsm = sm + 2 * 128 * TP2;       // [2][128][TP2]
    int tid = threadIdx.x;
    int m0 = blockIdx.y << 7, n0 = blockIdx.x << 7;
    int warp = tid >> 5, lane = tid & 31;
    int wm = (warp >> 2) << 6;             // 0 or 64
    int wn = (warp & 3) << 5;              // 0,32,64,96
    int g = lane >> 2, tg = lane & 3;

    float c[4][4][4];
#pragma unroll
    for (int mt = 0; mt < 4; mt++)
#pragma unroll
        for (int nt = 0; nt < 4; nt++)
#pragma unroll
            for (int i = 0; i < 4; i++) c[mt][nt][i] = 0.f;

    auto load_tile = [&](int st, int k0) {
#pragma unroll
        for (int i = 0; i < 2; i++) {
            int ch = tid + (i << 8);
            int row = ch >> 2, c4 = (ch & 3) << 2;
            unsigned sa = (unsigned)__cvta_generic_to_shared(&Asm[((st << 7) + row) * TP2 + c4]);
            asm volatile("cp.async.cg.shared.global [%0], [%1], 16;"
                         :: "r"(sa), "l"(A + (long)(m0 + row) * Kd + k0 + c4));
            unsigned sb = (unsigned)__cvta_generic_to_shared(&Bsm[((st << 7) + row) * TP2 + c4]);
            asm volatile("cp.async.cg.shared.global [%0], [%1], 16;"
                         :: "r"(sb), "l"(Bw + (long)(n0 + row) * Kd + k0 + c4));
        }
        asm volatile("cp.async.commit_group;");
    };

    int nk = Kd >> 4;
    load_tile(0, 0);
    for (int kt = 0; kt < nk; kt++) {
        asm volatile("cp.async.wait_group 0;");
        __syncthreads();
        if (kt + 1 < nk) load_tile((kt + 1) & 1, (kt + 1) << 4);
        const float* As = Asm + ((long)(kt & 1) << 7) * TP2;
        const float* Bs = Bsm + ((long)(kt & 1) << 7) * TP2;
#pragma unroll
        for (int kc = 0; kc < 2; kc++) {
            int kb = kc << 3;
            unsigned af[4][4], bf[4][2];
#pragma unroll
            for (int mt = 0; mt < 4; mt++) {
                int m = wm + (mt << 4);
                af[mt][0] = tf32cvt(As[(m + g) * TP2 + kb + tg]);
                af[mt][1] = tf32cvt(As[(m + g + 8) * TP2 + kb + tg]);
                af[mt][2] = tf32cvt(As[(m + g) * TP2 + kb + tg + 4]);
                af[mt][3] = tf32cvt(As[(m + g + 8) * TP2 + kb + tg + 4]);
            }
#pragma unroll
            for (int nt = 0; nt < 4; nt++) {
                int n = wn + (nt << 3);
                bf[nt][0] = tf32cvt(Bs[(n + g) * TP2 + kb + tg]);
                bf[nt][1] = tf32cvt(Bs[(n + g) * TP2 + kb + tg + 4]);
            }
#pragma unroll
            for (int mt = 0; mt < 4; mt++)
#pragma unroll
                for (int nt = 0; nt < 4; nt++) {
                    asm volatile(
                        "mma.sync.aligned.m16n8k8.row.col.f32.tf32.tf32.f32 "
                        "{%0,%1,%2,%3}, {%4,%5,%6,%7}, {%8,%9}, {%0,%1,%2,%3};"
                        : "+f"(c[mt][nt][0]), "+f"(c[mt][nt][1]),
                          "+f"(c[mt][nt][2]), "+f"(c[mt][nt][3])
                        : "r"(af[mt][0]), "r"(af[mt][1]), "r"(af[mt][2]), "r"(af[mt][3]),
                          "r"(bf[nt][0]), "r"(bf[nt][1]));
                }
        }
    }

#pragma unroll
    for (int mt = 0; mt < 4; mt++) {
#pragma unroll
        for (int nt = 0; nt < 4; nt++) {
#pragma unroll
            for (int i = 0; i < 4; i++) {
                int m = m0 + wm + (mt << 4) + g + ((i >> 1) << 3);
                int n = n0 + wn + (nt << 3) + (tg << 1) + (i & 1);
                float v = c[mt][nt][i];
                if (bias)  v += bias[n];
                if (bias2) v += bias2[n];
                if (res)   v += res[(long)m * Nd + n];
                v *= scale;
                if (act) v = 0.5f * v * (1.f + erff(v * 0.70710678118654752f));
                C[(long)m * Nd + n] = v;
            }
        }
    }
}

// LN with optional fused add (pos-emb broadcast over batch via addMod)
__global__ void ln_kernel(const float* __restrict__ in, const float* __restrict__ add,
                          int addMod, const float* __restrict__ gw,
                          const float* __restrict__ bw, float* __restrict__ out)
{
    int row = blockIdx.x;
    const float* xp = in + (long)row * HH;
    const float* ap = add ? add + (long)(row % addMod) * HH : (const float*)0;
    int tid = threadIdx.x;
    float v[4]; float s = 0.f, sq = 0.f;
#pragma unroll
    for (int i = 0; i < 4; i++) {
        int c = tid + (i << 8);
        float t = xp[c];
        if (ap) t += ap[c];
        v[i] = t; s += t; sq += t * t;
    }
#pragma unroll
    for (int o = 16; o > 0; o >>= 1) {
        s  += __shfl_xor_sync(0xffffffffu, s, o);
        sq += __shfl_xor_sync(0xffffffffu, sq, o);
    }
    __shared__ float red[18];
    int w = tid >> 5, l = tid & 31;
    if (l == 0) { red[w] = s; red[8 + w] = sq; }
    __syncthreads();
    if (tid == 0) {
        float ts = 0.f, tq = 0.f;
#pragma unroll
        for (int i = 0; i < 8; i++) { ts += red[i]; tq += red[8 + i]; }
        float mean = ts * (1.f / HH);
        float var  = tq * (1.f / HH) - mean * mean;
        red[16] = mean; red[17] = rsqrtf(var + 1e-7f);
    }
    __syncthreads();
    float mean = red[16], rstd = red[17];
    float* op = out + (long)row * HH;
#pragma unroll
    for (int i = 0; i < 4; i++) {
        int c = tid + (i << 8);
        op[c] = (v[i] - mean) * rstd * gw[c] + bw[c];
    }
}

// Fused scores + c2p + p2c + softmax, coalesced warp-per-k.
__global__ void attn_kernel(const float* __restrict__ qkv, const float* __restrict__ posk,
                            const float* __restrict__ posq, float* __restrict__ scores,
                            const float* __restrict__ qb)
{
    int row = blockIdx.x;
    int z = row >> 9, q = row & 511;
    int b = z >> 3, h = z & 7;
    int tid = threadIdx.x;
    int w = tid >> 5, lane = tid & 31;
    __shared__ float qs[DHH];
    __shared__ float sc[SS];
    __shared__ float red[17];
    const float* qkvq = qkv + ((long)(b * SS + q)) * (3 * HH) + h * DHH;
    if (tid < DHH) qs[tid] = (qkvq[tid] + qb[h * DHH + tid]) * INV_SCALE;
    __syncthreads();
    float4 qv = ((const float4*)qs)[lane];

#pragma unroll 2
    for (int i = 0; i < 64; i++) {
        int k = (w << 6) + i;
        int rel = q - k + 512;
        float4 kv = ((const float4*)(qkv + ((long)(b * SS + k)) * (3 * HH) + HH + h * DHH))[lane];
        float4 cv = ((const float4*)(posk + (long)rel * HH + h * DHH))[lane];
        float4 pv = ((const float4*)(posq + (long)rel * HH + h * DHH))[lane];
        float s = qv.x * (kv.x + cv.x) + kv.x * pv.x
                + qv.y * (kv.y + cv.y) + kv.y * pv.y
                + qv.z * (kv.z + cv.z) + kv.z * pv.z
                + qv.w * (kv.w + cv.w) + kv.w * pv.w;
#pragma unroll
        for (int o = 16; o > 0; o >>= 1) s += __shfl_xor_sync(0xffffffffu, s, o);
        if (lane == 0) sc[k] = s;
    }
    __syncthreads();

    float v0 = sc[tid], v1 = sc[tid + 256];
    float mx = fmaxf(v0, v1);
#pragma unroll
    for (int o = 16; o > 0; o >>= 1) mx = fmaxf(mx, __shfl_xor_sync(0xffffffffu, mx, o));
    if (lane == 0) red[w] = mx;
    __syncthreads();
    if (tid == 0) {
        float m2 = red[0];
#pragma unroll
        for (int i = 1; i < 8; i++) m2 = fmaxf(m2, red[i]);
        red[16] = m2;
    }
    __syncthreads();
    mx = red[16];
    float e0 = __expf(v0 - mx), e1 = __expf(v1 - mx);
    float s = e0 + e1;
#pragma unroll
    for (int o = 16; o > 0; o >>= 1) s += __shfl_xor_sync(0xffffffffu, s, o);
    __syncthreads();
    if (lane == 0) red[w] = s;
    __syncthreads();
    if (tid == 0) {
        float t = 0.f;
#pragma unroll
        for (int i = 0; i < 8; i++) t += red[i];
        red[16] = 1.f / t;
    }
    __syncthreads();
    float inv = red[16];
    float* srow = scores + (long)row * SS;
    srow[tid] = e0 * inv;
    srow[tid + 256] = e1 * inv;
}

// ctx2[b,q,h*128+d] = sum_k probs[z,q,k] * qkv_v[b,k,h*128+d]  + vb
__global__ void ctx_naive_kernel(const float* __restrict__ qkv, const float* __restrict__ scores,
                                 float* __restrict__ ctx2, const float* __restrict__ vb)
{
    __shared__ float ps[SS];
    int row = blockIdx.x;
    int z = row >> 9, q = row & 511;
    int b = z >> 3, h = z & 7;
    int tid = threadIdx.x;
    const float* srow = scores + (long)row * SS;
    for (int k = tid; k < SS; k += 128) ps[k] = srow[k];
    __syncthreads();
    int c = h * DHH + tid;
    const float* vp = qkv + (long)b * SS * (3 * HH) + 2 * HH + c;
    float acc = 0.f;
#pragma unroll 4
    for (int k = 0; k < SS; k++)
        acc = fmaf(ps[k], vp[(long)k * (3 * HH)], acc);
    acc += vb[c];
    ctx2[((long)(b * SS + q)) * HH + c] = acc;
}

// Persistent wavefront LSTM: 128 blocks, per-direction barriers (64 arrivals).
__global__ void LSTMDisentangledAttention_15049565405471_kernel(
    const float* __restrict__ xw,
    const float* __restrict__ WhhF,
    const float* __restrict__ WhhR,
    float* __restrict__ out)
{
    extern __shared__ float sm[];
    float* Wsh = sm;              // [512][32]
    float* hs  = sm + HD * 32;    // [8][512]
    int tid = threadIdx.x, blk = blockIdx.x;
    int dir = blk >> 6;
    int u0  = (blk & 63) << 3;
    int b = tid >> 5, lane = tid & 31;
    int ui = lane >> 2, gate = lane & 3;
    int r = (gate << 9) + u0 + ui;
    const float* Whh = dir ? WhhR : WhhF;
    const float* xwd = xw + (long)dir * MM * G4;
    float* seq = g_hseq + (long)dir * 513 * (BB * HD);
    unsigned int* bar = &g_bar2[dir];

    for (int idx = tid; idx < HD * 32; idx += 256) {
        int j = idx >> 5, l = idx & 31;
        int rl = ((l & 3) << 9) + u0 + (l >> 2);
        Wsh[idx] = Whh[(long)rl * HD + j];
    }

    float c = 0.f;
    __syncthreads();

    for (int t = 0; t < SS; t++) {
        int sI = dir ? (SS - 1 - t) : t;
        const float* hrd = seq + (long)t * (BB * HD);
        for (int idx = tid; idx < BB * HD; idx += 256)
            hs[idx] = hrd[idx];
        __syncthreads();

        float acc = xwd[((long)((b << 9) + sI)) * G4 + r];
        const float* hp = hs + (b << 9);
#pragma unroll 8
        for (int j = 0; j < HD; j++)
            acc = fmaf(Wsh[(j << 5) + lane], hp[j], acc);

        int base = lane & ~3;
        float vi = __shfl_sync(0xffffffffu, acc, base + 0);
        float vf = __shfl_sync(0xffffffffu, acc, base + 1);
        float vg = __shfl_sync(0xffffffffu, acc, base + 2);
        float vo = __shfl_sync(0xffffffffu, acc, base + 3);
        float ig = 1.f / (1.f + __expf(-vi));
        float fg = 1.f / (1.f + __expf(-vf));
        float gg = tanhf(vg);
        float og = 1.f / (1.f + __expf(-vo));
        c = fg * c + ig * gg;
        float hv = og * tanhf(c);
        if (gate == 0) {
            int u = u0 + ui;
            seq[(long)(t + 1) * (BB * HD) + (b << 9) + u] = hv;
            out[((long)((b << 9) + sI)) * HH + (dir << 9) + u] = hv;
        }
        __threadfence();
        __syncthreads();
        if (tid == 0) {
            atomicAdd(bar, 1u);
            unsigned target = (unsigned)(t + 1) * 64u;
            while (*((volatile unsigned int*)bar) < target) { }
            __threadfence();
        }
        __syncthreads();
    }
}

extern "C" void kernel_launch(void* const* d_in, const int* in_sizes, int n_in,
                              void* d_out, int out_size)
{
    (void)in_sizes; (void)n_in; (void)out_size;
    const float* x       = (const float*)d_in[0];
    const float* pos_emb = (const float*)d_in[1];
    const float* emb_g   = (const float*)d_in[2];
    const float* emb_b   = (const float*)d_in[3];
    const float* in_w    = (const float*)d_in[4];
    const float* q_bias  = (const float*)d_in[5];
    const float* v_bias  = (const float*)d_in[6];
    const float* rel_emb = (const float*)d_in[7];
    const float* posk_w  = (const float*)d_in[8];
    const float* posq_w  = (const float*)d_in[9];
    const float* posq_b  = (const float*)d_in[10];
    const float* ao_w    = (const float*)d_in[11];
    const float* ao_b    = (const float*)d_in[12];
    const float* aln_g   = (const float*)d_in[13];
    const float* aln_b   = (const float*)d_in[14];
    const float* it_w    = (const float*)d_in[15];
    const float* it_b    = (const float*)d_in[16];
    const float* fo_w    = (const float*)d_in[17];
    const float* fo_b    = (const float*)d_in[18];
    const float* fln_g   = (const float*)d_in[19];
    const float* fln_b   = (const float*)d_in[20];
    const float* Wih_f   = (const float*)d_in[21];
    const float* Whh_f   = (const float*)d_in[22];
    const float* bih_f   = (const float*)d_in[23];
    const float* bhh_f   = (const float*)d_in[24];
    const float* Wih_r   = (const float*)d_in[25];
    const float* Whh_r   = (const float*)d_in[26];
    const float* bih_r   = (const float*)d_in[27];
    const float* bhh_r   = (const float*)d_in[28];
    float* out = (float*)d_out;

    float *h1, *qkv, *posk, *posq, *scores, *ctx2, *t1, *y, *h2, *h3, *xw;
    void  *barp, *seqp;
    cudaGetSymbolAddress((void**)&h1,     g_h1);
    cudaGetSymbolAddress((void**)&qkv,    g_qkv);
    cudaGetSymbolAddress((void**)&posk,   g_posk);
    cudaGetSymbolAddress((void**)&posq,   g_posq);
    cudaGetSymbolAddress((void**)&scores, g_scores);
    cudaGetSymbolAddress((void**)&ctx2,   g_ctx2);
    cudaGetSymbolAddress((void**)&t1,     g_t1);
    cudaGetSymbolAddress((void**)&y,      g_y);
    cudaGetSymbolAddress((void**)&h2,     g_h2);
    cudaGetSymbolAddress((void**)&h3,     g_h3);
    cudaGetSymbolAddress((void**)&xw,     g_xw);
    cudaGetSymbolAddress(&barp,           g_bar2);
    cudaGetSymbolAddress(&seqp,           g_hseq);

    int gsmem = 2 * 2 * 128 * TP2 * 4;   // 40960 B -> 2 blocks/SM
    cudaFuncSetAttribute(tgemm_kernel, cudaFuncAttributeMaxDynamicSharedMemorySize, gsmem);

    // 1. h1 = LN(x + pos_emb)   (fused add)
    ln_kernel<<<MM, 256>>>(x, pos_emb, SS, emb_g, emb_b, h1);
    // 2. qkv = h1 @ in_w^T
    tgemm_kernel<<<dim3(IN3/128, MM/128), 256, gsmem>>>(h1, in_w, qkv, MM, IN3, HH,
        0, 0, 0, 1.f, 0);
    // 3. pos tables (pos_q pre-scaled)
    tgemm_kernel<<<dim3(HH/128, R2/128), 256, gsmem>>>(rel_emb, posk_w, posk, R2, HH, HH,
        0, 0, 0, 1.f, 0);
    tgemm_kernel<<<dim3(HH/128, R2/128), 256, gsmem>>>(rel_emb, posq_w, posq, R2, HH, HH,
        posq_b, 0, 0, INV_SCALE, 0);
    // 4. fused scores + c2p + p2c + softmax
    attn_kernel<<<BB*NHH*SS, 256>>>(qkv, posk, posq, scores, q_bias);
    // 5. ctx directly from qkv
    ctx_naive_kernel<<<BB*NHH*SS, 128>>>(qkv, scores, ctx2, v_bias);
    // 6. attn out + residual + LN
    tgemm_kernel<<<dim3(HH/128, MM/128), 256, gsmem>>>(ctx2, ao_w, y, MM, HH, HH,
        ao_b, 0, h1, 1.f, 0);
    ln_kernel<<<MM, 256>>>(y, 0, 1, aln_g, aln_b, h2);
    // 7. FFN
    tgemm_kernel<<<dim3(IN3/128, MM/128), 256, gsmem>>>(h2, it_w, t1, MM, IN3, HH,
        it_b, 0, 0, 1.f, 1);
    tgemm_kernel<<<dim3(HH/128, MM/128), 256, gsmem>>>(t1, fo_w, y, MM, HH, IN3,
        fo_b, 0, h2, 1.f, 0);
    ln_kernel<<<MM, 256>>>(y, 0, 1, fln_g, fln_b, h3);
    // 8. LSTM input projections
    tgemm_kernel<<<dim3(G4/128, MM/128), 256, gsmem>>>(h3, Wih_f, xw, MM, G4, HH,
        bih_f, bhh_f, 0, 1.f, 0);
    tgemm_kernel<<<dim3(G4/128, MM/128), 256, gsmem>>>(h3, Wih_r, xw + (long)MM*G4, MM, G4, HH,
        bih_r, bhh_r, 0, 1.f, 0);
    // 9. persistent wavefront LSTM
    cudaMemsetAsync(barp, 0, 2 * sizeof(unsigned int), 0);
    cudaMemsetAsync(seqp, 0, sizeof(float) * BB * HD, 0);
    cudaMemsetAsync((char*)seqp + sizeof(float) * 513 * BB * HD, 0, sizeof(float) * BB * HD, 0);
    int lsmem = HD * 32 * 4 + BB * HD * 4;
    cudaFuncSetAttribute(LSTMDisentangledAttention_15049565405471_kernel,
                         cudaFuncAttributeMaxDynamicSharedMemorySize, lsmem);
    LSTMDisentangledAttention_15049565405471_kernel<<<128, 256, lsmem>>>(xw, Whh_f, Whh_r, out);
}